// round 3
// baseline (speedup 1.0000x reference)
#include <cuda_runtime.h>
#include <cuda_fp16.h>

#define BB 2
#define LL 384
#define HH 8
#define DD 64
#define HIDN 512
#define BH (BB*HH)          // 16
#define MROWS (BB*LL)       // 768
#define X_ELEMS (MROWS*HIDN)    // 393216
#define A_ELEMS (BH*LL*LL)      // 2359296

// -------- scratch (no dynamic allocation allowed) --------
__device__ float g_tQ [BH*LL*DD];   // [bh][l][d]
__device__ float g_tKT[BH*DD*LL];   // [bh][d][k]  (transposed for coalesced energy loads)
__device__ float g_V  [BH*LL*DD];   // [bh][l][d]
__device__ float g_X  [X_ELEMS];
__device__ float g_attn[A_ELEMS];
__device__ float g_Wfq[HIDN*HIDN];  // fused W1@Wq per head
__device__ float g_Wfk[HIDN*HIDN];  // fused W2@Wk per head
__device__ float g_bfq[HIDN];
__device__ float g_bfk[HIDN];

__device__ __forceinline__ __half2 ath_h2tanh(__half2 x) {
    unsigned xi = *(unsigned*)&x, yi;
    asm("tanh.approx.f16x2 %0, %1;" : "=r"(yi) : "r"(xi));
    return *(__half2*)&yi;
}

// ---------------- prep: fused per-head weights ----------------
// Wout[h*64+i][c] = sum_j Wh[i][j] * Wsrc[h*64+j][c]
// bout[h*64+i]    = bh_[i] + sum_j Wh[i][j] * bsrc[h*64+j]
__global__ void __launch_bounds__(256) prep_fuse(
    const float* __restrict__ W1, const float* __restrict__ b1,
    const float* __restrict__ W2, const float* __restrict__ b2,
    const float* __restrict__ Wq, const float* __restrict__ bq,
    const float* __restrict__ Wk, const float* __restrict__ bk)
{
    int h = blockIdx.x;
    int sel = blockIdx.y;
    const float* Wh   = sel ? W2 : W1;
    const float* bh_  = sel ? b2 : b1;
    const float* Wsrc = sel ? Wk : Wq;
    const float* bsrc = sel ? bk : bq;
    float* Wout = sel ? g_Wfk : g_Wfq;
    float* bout = sel ? g_bfk : g_bfq;
    __shared__ float Ws[DD][DD + 1];
    __shared__ float Ts[DD][DD + 1];
    int tid = threadIdx.x;
    for (int t = tid; t < DD * DD; t += 256) Ws[t >> 6][t & 63] = Wh[t];
    __syncthreads();
    if (tid < DD) {
        float acc = bh_[tid];
        for (int j = 0; j < DD; j++) acc += Ws[tid][j] * bsrc[h * DD + j];
        bout[h * DD + tid] = acc;
    }
    int i = tid & 63;
    int g = tid >> 6;     // 0..3
    for (int c0 = 0; c0 < HIDN; c0 += DD) {
        __syncthreads();
        for (int t = tid; t < DD * DD; t += 256)
            Ts[t >> 6][t & 63] = Wsrc[(h * DD + (t >> 6)) * HIDN + c0 + (t & 63)];
        __syncthreads();
#pragma unroll
        for (int cc = 0; cc < 16; cc++) {
            int c = g * 16 + cc;
            float acc = 0.f;
#pragma unroll 8
            for (int j = 0; j < DD; j++) acc = fmaf(Ws[i][j], Ts[j][c], acc);
            Wout[(h * DD + i) * HIDN + c0 + c] = acc;
        }
    }
}

// ---------------- big GEMM: out = X @ W^T + bias ----------------
// mode 0: plain [m, HIDN]; mode 1: head-major [bh][l][d]; mode 2: [bh][d][l]
template<int BM, int TM>
__global__ void __launch_bounds__(256) gemm_big(
    const float* __restrict__ X0, const float* __restrict__ Wm0, const float* __restrict__ B0, float* __restrict__ O0, int md0,
    const float* __restrict__ X1, const float* __restrict__ Wm1, const float* __restrict__ B1, float* __restrict__ O1, int md1,
    const float* __restrict__ X2, const float* __restrict__ Wm2, const float* __restrict__ B2, float* __restrict__ O2, int md2)
{
    const int BK = 32;
    int z = blockIdx.z;
    const float* X  = z == 0 ? X0  : (z == 1 ? X1  : X2);
    const float* W  = z == 0 ? Wm0 : (z == 1 ? Wm1 : Wm2);
    const float* Bi = z == 0 ? B0  : (z == 1 ? B1  : B2);
    float*       O  = z == 0 ? O0  : (z == 1 ? O1  : O2);
    int        mode = z == 0 ? md0 : (z == 1 ? md1 : md2);

    __shared__ float As[BK][BM + 4];
    __shared__ float Bs[BK][64 + 4];
    int tid = threadIdx.x;
    int tx = tid & 15;        // n
    int ty = tid >> 4;        // m
    int m0 = blockIdx.y * BM, n0 = blockIdx.x * 64;
    float acc[TM][4] = {};

    for (int kk = 0; kk < HIDN; kk += BK) {
#pragma unroll
        for (int i = 0; i < BM * BK / 4 / 256; i++) {
            int idx = tid + i * 256;
            int r = idx >> 3, c4 = idx & 7;
            float4 v = *(const float4*)&X[(m0 + r) * HIDN + kk + c4 * 4];
            As[c4 * 4 + 0][r] = v.x; As[c4 * 4 + 1][r] = v.y;
            As[c4 * 4 + 2][r] = v.z; As[c4 * 4 + 3][r] = v.w;
        }
#pragma unroll
        for (int i = 0; i < 2; i++) {
            int idx = tid + i * 256;
            int r = idx >> 3, c4 = idx & 7;
            float4 v = *(const float4*)&W[(n0 + r) * HIDN + kk + c4 * 4];
            Bs[c4 * 4 + 0][r] = v.x; Bs[c4 * 4 + 1][r] = v.y;
            Bs[c4 * 4 + 2][r] = v.z; Bs[c4 * 4 + 3][r] = v.w;
        }
        __syncthreads();
#pragma unroll 8
        for (int kc = 0; kc < BK; kc++) {
            float a[TM], b[4];
            *(float4*)&a[0] = *(const float4*)&As[kc][ty * TM];
            if (TM == 8) *(float4*)&a[4] = *(const float4*)&As[kc][ty * TM + 4];
            *(float4*)&b[0] = *(const float4*)&Bs[kc][tx * 4];
#pragma unroll
            for (int i = 0; i < TM; i++)
#pragma unroll
                for (int j = 0; j < 4; j++)
                    acc[i][j] = fmaf(a[i], b[j], acc[i][j]);
        }
        __syncthreads();
    }

    float4 bias4 = *(const float4*)&Bi[n0 + tx * 4];
#pragma unroll
    for (int i = 0; i < TM; i++) {
        int m = m0 + ty * TM + i;
        int b = m / LL, l = m - b * LL;
        float4 v;
        v.x = acc[i][0] + bias4.x; v.y = acc[i][1] + bias4.y;
        v.z = acc[i][2] + bias4.z; v.w = acc[i][3] + bias4.w;
        if (mode == 0) {
            *(float4*)&O[m * HIDN + n0 + tx * 4] = v;
        } else if (mode == 1) {
            int h = n0 >> 6;
            *(float4*)&O[((b * HH + h) * LL + l) * DD + tx * 4] = v;
        } else {
            int h = n0 >> 6;
            float* base = O + (b * HH + h) * DD * LL + l;
            base[(tx * 4 + 0) * LL] = v.x;
            base[(tx * 4 + 1) * LL] = v.y;
            base[(tx * 4 + 2) * LL] = v.z;
            base[(tx * 4 + 3) * LL] = v.w;
        }
    }
}

// ---------------- energy + softmax (f16x2 tanh) ----------------
__global__ void __launch_bounds__(256) energy_softmax(
    const int* __restrict__ mask, const float* __restrict__ vw,
    float* __restrict__ attn)
{
    __shared__ float   sQ[16][DD + 1];
    __shared__ __half2 sKh[DD][33];
    __shared__ float   sE[16][LL + 1];
    __shared__ __half2 sVW[DD];
    int tx = threadIdx.x, ty = threadIdx.y;  // (16,16)
    int tid = ty * 16 + tx;
    int bh = blockIdx.y, b = bh >> 3;
    int q0 = blockIdx.x * 16;
    if (tid < DD) sVW[tid] = __float2half2_rn(vw[tid]);
#pragma unroll
    for (int i = 0; i < 4; i++) {
        int idx = tid + i * 256;
        sQ[idx >> 6][idx & 63] = g_tQ[(bh * LL + q0) * DD + idx];
    }
    __syncthreads();
    const float* tKT = g_tKT + bh * DD * LL;
    for (int kc = 0; kc < LL; kc += DD) {
#pragma unroll
        for (int i = 0; i < 8; i++) {
            int idx = tid + i * 256;            // 0..2047
            int d = idx >> 5, p = idx & 31;
            float2 kv = *(const float2*)&tKT[d * LL + kc + p * 2];
            sKh[d][p] = __floats2half2_rn(kv.x, kv.y);
        }
        __syncthreads();
        __half2 acc0 = __floats2half2_rn(0.f, 0.f), acc1 = acc0;
#pragma unroll
        for (int d = 0; d < DD; d++) {
            __half2 q2 = __float2half2_rn(sQ[ty][d]);
            __half2 w2 = sVW[d];
            acc0 = __hfma2(w2, ath_h2tanh(__hadd2(q2, sKh[d][2 * tx])), acc0);
            acc1 = __hfma2(w2, ath_h2tanh(__hadd2(q2, sKh[d][2 * tx + 1])), acc1);
        }
        float2 e0 = __half22float2(acc0);
        float2 e1 = __half22float2(acc1);
        sE[ty][kc + 4 * tx + 0] = e0.x;
        sE[ty][kc + 4 * tx + 1] = e0.y;
        sE[ty][kc + 4 * tx + 2] = e1.x;
        sE[ty][kc + 4 * tx + 3] = e1.y;
        __syncthreads();
    }
    // softmax over 384 cols; row ty handled by 16 lanes (half-warp)
    float ev[24];
    float mx = -3.0e38f;
#pragma unroll
    for (int i = 0; i < 24; i++) {
        int j = tx + i * 16;
        float e = sE[ty][j];
        if (__ldg(&mask[b * LL + j]) == 0) e = -1e10f;
        ev[i] = e;
        mx = fmaxf(mx, e);
    }
#pragma unroll
    for (int o = 8; o > 0; o >>= 1) mx = fmaxf(mx, __shfl_xor_sync(0xffffffffu, mx, o));
    float sum = 0.f;
#pragma unroll
    for (int i = 0; i < 24; i++) { ev[i] = __expf(ev[i] - mx); sum += ev[i]; }
#pragma unroll
    for (int o = 8; o > 0; o >>= 1) sum += __shfl_xor_sync(0xffffffffu, sum, o);
    float inv = __frcp_rn(sum);
#pragma unroll
    for (int i = 0; i < 24; i++) sE[ty][tx + i * 16] = ev[i] * inv;
    __syncthreads();
    float* dst = attn + (bh * LL + q0) * LL;
    for (int idx = tid; idx < 16 * LL; idx += 256) {
        int r = idx / LL, j = idx - r * LL;
        dst[r * LL + j] = sE[r][j];
    }
}

// ---------------- AV: x = attn @ V ----------------
__global__ void __launch_bounds__(256) av_kernel(const float* __restrict__ attn)
{
    __shared__ float sA[DD][DD + 1];
    __shared__ float sV[DD][DD + 1];
    int tx = threadIdx.x, ty = threadIdx.y;  // (64,4)
    int tid = ty * 64 + tx;
    int bh = blockIdx.y;
    int b = bh >> 3, h = bh & 7;
    int q0 = blockIdx.x * 64;
    float acc[16] = {};
    for (int kc = 0; kc < LL; kc += 64) {
#pragma unroll
        for (int i = 0; i < 16; i++) {
            int idx = tid + i * 256;
            int r = idx >> 6, c = idx & 63;
            sA[r][c] = attn[(bh * LL + q0 + r) * LL + kc + c];
            sV[r][c] = g_V[(bh * LL + kc + r) * DD + c];
        }
        __syncthreads();
        for (int k = 0; k < 64; k++) {
            float v = sV[k][tx];
#pragma unroll
            for (int r = 0; r < 16; r++)
                acc[r] = fmaf(sA[ty + r * 4][k], v, acc[r]);
        }
        __syncthreads();
    }
#pragma unroll
    for (int r = 0; r < 16; r++) {
        int q = q0 + ty + r * 4;
        g_X[(b * LL + q) * HIDN + h * DD + tx] = acc[r];
    }
}

extern "C" void kernel_launch(void* const* d_in, const int* in_sizes, int n_in,
                              void* d_out, int out_size)
{
    const float* query = (const float*)d_in[0];
    const float* key_  = (const float*)d_in[1];
    const float* value = (const float*)d_in[2];
    const int*   mask  = (const int*)  d_in[3];
    const float* Wq = (const float*)d_in[4];
    const float* bq = (const float*)d_in[5];
    const float* Wk = (const float*)d_in[6];
    const float* bk = (const float*)d_in[7];
    const float* Wv = (const float*)d_in[8];
    const float* bv = (const float*)d_in[9];
    const float* Wo = (const float*)d_in[10];
    const float* bo = (const float*)d_in[11];
    const float* W1 = (const float*)d_in[12];
    const float* b1 = (const float*)d_in[13];
    const float* W2 = (const float*)d_in[14];
    const float* b2 = (const float*)d_in[15];
    const float* vw = (const float*)d_in[16];
    (void)d_in[17]; // vb cancels in softmax; raw energy never output
    (void)in_sizes; (void)n_in;

    float* out = (float*)d_out;

    float *gtQ, *gtKT, *gV, *gX, *gA, *gWfq, *gWfk, *gbfq, *gbfk;
    cudaGetSymbolAddress((void**)&gtQ,  g_tQ);
    cudaGetSymbolAddress((void**)&gtKT, g_tKT);
    cudaGetSymbolAddress((void**)&gV,   g_V);
    cudaGetSymbolAddress((void**)&gX,   g_X);
    cudaGetSymbolAddress((void**)&gA,   g_attn);
    cudaGetSymbolAddress((void**)&gWfq, g_Wfq);
    cudaGetSymbolAddress((void**)&gWfk, g_Wfk);
    cudaGetSymbolAddress((void**)&gbfq, g_bfq);
    cudaGetSymbolAddress((void**)&gbfk, g_bfk);

    float* attn_dst = (out_size >= X_ELEMS + A_ELEMS) ? (out + X_ELEMS) : gA;

    // 1) fuse W1@Wq and W2@Wk  (16 small blocks)
    prep_fuse<<<dim3(HH, 2), 256>>>(W1, b1, W2, b2, Wq, bq, Wk, bk);

    // 2) fused tQ / tK^T / V projection — one wave of 144 blocks
    gemm_big<128, 8><<<dim3(HIDN / 64, MROWS / 128, 3), 256>>>(
        query, gWfq, gbfq, gtQ,  1,
        key_,  gWfk, gbfk, gtKT, 2,
        value, Wv,   bv,   gV,   1);

    // 3) energy + softmax (MUFU f16x2)
    energy_softmax<<<dim3(LL / 16, BH), dim3(16, 16)>>>(mask, vw, attn_dst);

    // 4) attn @ V
    av_kernel<<<dim3(LL / 64, BH), dim3(64, 4)>>>(attn_dst);

    // 5) output projection
    gemm_big<64, 4><<<dim3(HIDN / 64, MROWS / 64, 1), 256>>>(
        gX, Wo, bo, out, 0,
        gX, Wo, bo, out, 0,
        gX, Wo, bo, out, 0);
}

// round 4
// speedup vs baseline: 1.2211x; 1.2211x over previous
#include <cuda_runtime.h>
#include <cuda_fp16.h>

#define BB 2
#define LL 384
#define HH 8
#define DD 64
#define HIDN 512
#define BH (BB*HH)          // 16
#define MROWS (BB*LL)       // 768
#define X_ELEMS (MROWS*HIDN)    // 393216
#define A_ELEMS (BH*LL*LL)      // 2359296

// -------- scratch (no dynamic allocation allowed) --------
__device__ float g_tQ [BH*LL*DD];   // [bh][l][d]
__device__ float g_tKT[BH*DD*LL];   // [bh][d][k]
__device__ float g_V  [BH*LL*DD];   // [bh][l][d]
__device__ float g_X  [X_ELEMS];
__device__ float g_attn[A_ELEMS];
__device__ float g_Wfq[HIDN*HIDN];
__device__ float g_Wfk[HIDN*HIDN];
__device__ float g_bfq[HIDN];
__device__ float g_bfk[HIDN];

__device__ __forceinline__ __half2 ath_h2tanh(__half2 x) {
    unsigned xi = *(unsigned*)&x, yi;
    asm("tanh.approx.f16x2 %0, %1;" : "=r"(yi) : "r"(xi));
    return *(__half2*)&yi;
}

// ---------------- prep: fused per-head weights ----------------
__global__ void __launch_bounds__(256) prep_fuse(
    const float* __restrict__ W1, const float* __restrict__ b1,
    const float* __restrict__ W2, const float* __restrict__ b2,
    const float* __restrict__ Wq, const float* __restrict__ bq,
    const float* __restrict__ Wk, const float* __restrict__ bk)
{
    int h = blockIdx.x;
    int sel = blockIdx.y;
    const float* Wh   = sel ? W2 : W1;
    const float* bh_  = sel ? b2 : b1;
    const float* Wsrc = sel ? Wk : Wq;
    const float* bsrc = sel ? bk : bq;
    float* Wout = sel ? g_Wfk : g_Wfq;
    float* bout = sel ? g_bfk : g_bfq;
    __shared__ float Ws[DD][DD + 1];
    __shared__ float Ts[DD][DD + 1];
    int tid = threadIdx.x;
    for (int t = tid; t < DD * DD; t += 256) Ws[t >> 6][t & 63] = Wh[t];
    __syncthreads();
    if (tid < DD) {
        float acc = bh_[tid];
        for (int j = 0; j < DD; j++) acc += Ws[tid][j] * bsrc[h * DD + j];
        bout[h * DD + tid] = acc;
    }
    int i = tid & 63;
    int g = tid >> 6;
    for (int c0 = 0; c0 < HIDN; c0 += DD) {
        __syncthreads();
        for (int t = tid; t < DD * DD; t += 256)
            Ts[t >> 6][t & 63] = Wsrc[(h * DD + (t >> 6)) * HIDN + c0 + (t & 63)];
        __syncthreads();
#pragma unroll
        for (int cc = 0; cc < 16; cc++) {
            int c = g * 16 + cc;
            float acc = 0.f;
#pragma unroll 8
            for (int j = 0; j < DD; j++) acc = fmaf(Ws[i][j], Ts[j][c], acc);
            Wout[(h * DD + i) * HIDN + c0 + c] = acc;
        }
    }
}

// ---------------- GEMM: out = X @ W^T + bias (64x64 tiles, 4x4/thread) ----------------
// mode 0: plain [m, HIDN]; mode 1: head-major [bh][l][d]; mode 2: [bh][d][l]
__global__ void __launch_bounds__(256) gemm_big(
    const float* __restrict__ X0, const float* __restrict__ Wm0, const float* __restrict__ B0, float* __restrict__ O0, int md0,
    const float* __restrict__ X1, const float* __restrict__ Wm1, const float* __restrict__ B1, float* __restrict__ O1, int md1,
    const float* __restrict__ X2, const float* __restrict__ Wm2, const float* __restrict__ B2, float* __restrict__ O2, int md2)
{
    const int BK = 32;
    int z = blockIdx.z;
    const float* X  = z == 0 ? X0  : (z == 1 ? X1  : X2);
    const float* W  = z == 0 ? Wm0 : (z == 1 ? Wm1 : Wm2);
    const float* Bi = z == 0 ? B0  : (z == 1 ? B1  : B2);
    float*       O  = z == 0 ? O0  : (z == 1 ? O1  : O2);
    int        mode = z == 0 ? md0 : (z == 1 ? md1 : md2);

    __shared__ float As[BK][64 + 4];
    __shared__ float Bs[BK][64 + 4];
    int tid = threadIdx.x;
    int tx = tid & 15;        // n
    int ty = tid >> 4;        // m
    int m0 = blockIdx.y * 64, n0 = blockIdx.x * 64;
    float acc[4][4] = {};

    for (int kk = 0; kk < HIDN; kk += BK) {
#pragma unroll
        for (int i = 0; i < 2; i++) {
            int idx = tid + i * 256;
            int r = idx >> 3, c4 = idx & 7;
            float4 v = *(const float4*)&X[(m0 + r) * HIDN + kk + c4 * 4];
            As[c4 * 4 + 0][r] = v.x; As[c4 * 4 + 1][r] = v.y;
            As[c4 * 4 + 2][r] = v.z; As[c4 * 4 + 3][r] = v.w;
        }
#pragma unroll
        for (int i = 0; i < 2; i++) {
            int idx = tid + i * 256;
            int r = idx >> 3, c4 = idx & 7;
            float4 v = *(const float4*)&W[(n0 + r) * HIDN + kk + c4 * 4];
            Bs[c4 * 4 + 0][r] = v.x; Bs[c4 * 4 + 1][r] = v.y;
            Bs[c4 * 4 + 2][r] = v.z; Bs[c4 * 4 + 3][r] = v.w;
        }
        __syncthreads();
#pragma unroll 8
        for (int kc = 0; kc < BK; kc++) {
            float a[4], b[4];
            *(float4*)&a[0] = *(const float4*)&As[kc][ty * 4];
            *(float4*)&b[0] = *(const float4*)&Bs[kc][tx * 4];
#pragma unroll
            for (int i = 0; i < 4; i++)
#pragma unroll
                for (int j = 0; j < 4; j++)
                    acc[i][j] = fmaf(a[i], b[j], acc[i][j]);
        }
        __syncthreads();
    }

    float4 bias4 = *(const float4*)&Bi[n0 + tx * 4];
#pragma unroll
    for (int i = 0; i < 4; i++) {
        int m = m0 + ty * 4 + i;
        int b = m / LL, l = m - b * LL;
        float4 v;
        v.x = acc[i][0] + bias4.x; v.y = acc[i][1] + bias4.y;
        v.z = acc[i][2] + bias4.z; v.w = acc[i][3] + bias4.w;
        if (mode == 0) {
            *(float4*)&O[m * HIDN + n0 + tx * 4] = v;
        } else if (mode == 1) {
            int h = n0 >> 6;
            *(float4*)&O[((b * HH + h) * LL + l) * DD + tx * 4] = v;
        } else {
            int h = n0 >> 6;
            float* base = O + (b * HH + h) * DD * LL + l;
            base[(tx * 4 + 0) * LL] = v.x;
            base[(tx * 4 + 1) * LL] = v.y;
            base[(tx * 4 + 2) * LL] = v.z;
            base[(tx * 4 + 3) * LL] = v.w;
        }
    }
}

// ---------------- energy + softmax + AV, fully fused ----------------
// one block = 16 q-rows of one (b,h): energy (f16x2 tanh), mask, softmax,
// write attn tile, then x_tile = attn_tile @ V directly from shared.
__global__ void __launch_bounds__(256) energy_softmax_av(
    const int* __restrict__ mask, const float* __restrict__ vw,
    float* __restrict__ attn)
{
    __shared__ float   sQ[16][DD + 1];
    __shared__ __half2 sKh[DD][33];
    __shared__ float   sE[16][LL + 1];
    __shared__ __half2 sVW[DD];
    __shared__ float   sV[DD][DD];
    int tx = threadIdx.x, ty = threadIdx.y;  // (16,16)
    int tid = ty * 16 + tx;
    int bh = blockIdx.y, b = bh >> 3, h = bh & 7;
    int q0 = blockIdx.x * 16;
    if (tid < DD) sVW[tid] = __float2half2_rn(vw[tid]);
#pragma unroll
    for (int i = 0; i < 4; i++) {
        int idx = tid + i * 256;
        sQ[idx >> 6][idx & 63] = g_tQ[(bh * LL + q0) * DD + idx];
    }
    __syncthreads();
    const float* tKT = g_tKT + bh * DD * LL;
    for (int kc = 0; kc < LL; kc += DD) {
#pragma unroll
        for (int i = 0; i < 8; i++) {
            int idx = tid + i * 256;            // 0..2047
            int d = idx >> 5, p = idx & 31;
            float2 kv = *(const float2*)&tKT[d * LL + kc + p * 2];
            sKh[d][p] = __floats2half2_rn(kv.x, kv.y);
        }
        __syncthreads();
        __half2 acc0 = __floats2half2_rn(0.f, 0.f), acc1 = acc0;
#pragma unroll
        for (int d = 0; d < DD; d++) {
            __half2 q2 = __float2half2_rn(sQ[ty][d]);
            __half2 w2 = sVW[d];
            acc0 = __hfma2(w2, ath_h2tanh(__hadd2(q2, sKh[d][2 * tx])), acc0);
            acc1 = __hfma2(w2, ath_h2tanh(__hadd2(q2, sKh[d][2 * tx + 1])), acc1);
        }
        float2 e0 = __half22float2(acc0);
        float2 e1 = __half22float2(acc1);
        sE[ty][kc + 4 * tx + 0] = e0.x;
        sE[ty][kc + 4 * tx + 1] = e0.y;
        sE[ty][kc + 4 * tx + 2] = e1.x;
        sE[ty][kc + 4 * tx + 3] = e1.y;
        __syncthreads();
    }
    // softmax over 384 cols; row ty handled by 16 lanes (half-warp)
    float ev[24];
    float mx = -3.0e38f;
#pragma unroll
    for (int i = 0; i < 24; i++) {
        int j = tx + i * 16;
        float e = sE[ty][j];
        if (__ldg(&mask[b * LL + j]) == 0) e = -1e10f;
        ev[i] = e;
        mx = fmaxf(mx, e);
    }
#pragma unroll
    for (int o = 8; o > 0; o >>= 1) mx = fmaxf(mx, __shfl_xor_sync(0xffffffffu, mx, o));
    float sum = 0.f;
#pragma unroll
    for (int i = 0; i < 24; i++) { ev[i] = __expf(ev[i] - mx); sum += ev[i]; }
#pragma unroll
    for (int o = 8; o > 0; o >>= 1) sum += __shfl_xor_sync(0xffffffffu, sum, o);
    float inv = __frcp_rn(sum);
#pragma unroll
    for (int i = 0; i < 24; i++) sE[ty][tx + i * 16] = ev[i] * inv;
    __syncthreads();
    // coalesced store of the 16 x 384 attention tile
    float* dst = attn + (bh * LL + q0) * LL;
    for (int idx = tid; idx < 16 * LL; idx += 256) {
        int r = idx / LL, j = idx - r * LL;
        dst[r * LL + j] = sE[r][j];
    }
    // ---- AV: x_tile[16][64] = sE(16x384) @ V(384x64), stream V in 64-row chunks ----
    float acc[4] = {0.f, 0.f, 0.f, 0.f};
    const float* Vb = g_V + bh * LL * DD;
    for (int kc = 0; kc < LL; kc += DD) {
        __syncthreads();
#pragma unroll
        for (int i = 0; i < 4; i++) {
            int idx = tid + i * 256;             // 0..1023 -> float4 units
            int r = idx >> 4, c4 = idx & 15;
            *(float4*)&sV[r][c4 * 4] = *(const float4*)&Vb[(kc + r) * DD + c4 * 4];
        }
        __syncthreads();
#pragma unroll 4
        for (int k = 0; k < DD; k++) {
            float a = sE[ty][kc + k];
            float4 v = *(const float4*)&sV[k][tx * 4];
            acc[0] = fmaf(a, v.x, acc[0]);
            acc[1] = fmaf(a, v.y, acc[1]);
            acc[2] = fmaf(a, v.z, acc[2]);
            acc[3] = fmaf(a, v.w, acc[3]);
        }
    }
    int q = q0 + ty;
    float4 xo; xo.x = acc[0]; xo.y = acc[1]; xo.z = acc[2]; xo.w = acc[3];
    *(float4*)&g_X[(b * LL + q) * HIDN + h * DD + tx * 4] = xo;
}

extern "C" void kernel_launch(void* const* d_in, const int* in_sizes, int n_in,
                              void* d_out, int out_size)
{
    const float* query = (const float*)d_in[0];
    const float* key_  = (const float*)d_in[1];
    const float* value = (const float*)d_in[2];
    const int*   mask  = (const int*)  d_in[3];
    const float* Wq = (const float*)d_in[4];
    const float* bq = (const float*)d_in[5];
    const float* Wk = (const float*)d_in[6];
    const float* bk = (const float*)d_in[7];
    const float* Wv = (const float*)d_in[8];
    const float* bv = (const float*)d_in[9];
    const float* Wo = (const float*)d_in[10];
    const float* bo = (const float*)d_in[11];
    const float* W1 = (const float*)d_in[12];
    const float* b1 = (const float*)d_in[13];
    const float* W2 = (const float*)d_in[14];
    const float* b2 = (const float*)d_in[15];
    const float* vw = (const float*)d_in[16];
    (void)d_in[17]; // vb cancels in softmax; raw energy never output
    (void)in_sizes; (void)n_in;

    float* out = (float*)d_out;

    float *gtQ, *gtKT, *gV, *gX, *gA, *gWfq, *gWfk, *gbfq, *gbfk;
    cudaGetSymbolAddress((void**)&gtQ,  g_tQ);
    cudaGetSymbolAddress((void**)&gtKT, g_tKT);
    cudaGetSymbolAddress((void**)&gV,   g_V);
    cudaGetSymbolAddress((void**)&gX,   g_X);
    cudaGetSymbolAddress((void**)&gA,   g_attn);
    cudaGetSymbolAddress((void**)&gWfq, g_Wfq);
    cudaGetSymbolAddress((void**)&gWfk, g_Wfk);
    cudaGetSymbolAddress((void**)&gbfq, g_bfq);
    cudaGetSymbolAddress((void**)&gbfk, g_bfk);

    float* attn_dst = (out_size >= X_ELEMS + A_ELEMS) ? (out + X_ELEMS) : gA;

    // 1) fuse W1@Wq and W2@Wk
    prep_fuse<<<dim3(HH, 2), 256>>>(W1, b1, W2, b2, Wq, bq, Wk, bk);

    // 2) fused tQ / tK^T / V projection — 288 blocks (~2/SM)
    gemm_big<<<dim3(HIDN / 64, MROWS / 64, 3), 256>>>(
        query, gWfq, gbfq, gtQ,  1,
        key_,  gWfk, gbfk, gtKT, 2,
        value, Wv,   bv,   gV,   1);

    // 3) energy + softmax + AV fused (384 blocks)
    energy_softmax_av<<<dim3(LL / 16, BH), dim3(16, 16)>>>(mask, vw, attn_dst);

    // 4) output projection (96 blocks)
    gemm_big<<<dim3(HIDN / 64, MROWS / 64, 1), 256>>>(
        gX, Wo, bo, out, 0,
        gX, Wo, bo, out, 0,
        gX, Wo, bo, out, 0);
}

// round 5
// speedup vs baseline: 1.9993x; 1.6372x over previous
#include <cuda_runtime.h>
#include <cuda_fp16.h>

#define BB 2
#define LL 384
#define HH 8
#define DD 64
#define HIDN 512
#define BH (BB*HH)          // 16
#define MROWS (BB*LL)       // 768
#define X_ELEMS (MROWS*HIDN)    // 393216
#define A_ELEMS (BH*LL*LL)      // 2359296

// -------- scratch (no dynamic allocation allowed) --------
__device__ float g_tQ [BH*LL*DD];   // [bh][l][d]
__device__ float g_tKT[BH*DD*LL];   // [bh][d][k]
__device__ float g_V  [BH*LL*DD];   // [bh][l][d]
__device__ float g_X  [X_ELEMS];
__device__ float g_attn[A_ELEMS];
__device__ float g_Wfq[HIDN*HIDN];
__device__ float g_Wfk[HIDN*HIDN];
__device__ float g_bfq[HIDN];
__device__ float g_bfk[HIDN];

__device__ __forceinline__ __half2 ath_h2tanh(__half2 x) {
    unsigned xi = *(unsigned*)&x, yi;
    asm("tanh.approx.f16x2 %0, %1;" : "=r"(yi) : "r"(xi));
    return *(__half2*)&yi;
}
__device__ __forceinline__ unsigned f2tf32(float f) {
    unsigned u;
    asm("cvt.rna.tf32.f32 %0, %1;" : "=r"(u) : "f"(f));
    return u;
}
__device__ __forceinline__ void mma_tf32(float* c, const unsigned* a, const unsigned* b) {
    asm volatile(
        "mma.sync.aligned.m16n8k8.row.col.f32.tf32.tf32.f32 "
        "{%0,%1,%2,%3}, {%4,%5,%6,%7}, {%8,%9}, {%0,%1,%2,%3};"
        : "+f"(c[0]), "+f"(c[1]), "+f"(c[2]), "+f"(c[3])
        : "r"(a[0]), "r"(a[1]), "r"(a[2]), "r"(a[3]), "r"(b[0]), "r"(b[1]));
}

// ---------------- prep: fused per-head weights (parallel over col blocks) ----------------
// Wout[h*64+i][c] = sum_j Wh[i][j] * Wsrc[h*64+j][c]
__global__ void __launch_bounds__(256) prep_fuse(
    const float* __restrict__ W1, const float* __restrict__ b1,
    const float* __restrict__ W2, const float* __restrict__ b2,
    const float* __restrict__ Wq, const float* __restrict__ bq,
    const float* __restrict__ Wk, const float* __restrict__ bk)
{
    int h   = blockIdx.x;
    int sel = blockIdx.y;
    int c0  = blockIdx.z * 64;
    const float* Wh   = sel ? W2 : W1;
    const float* bh_  = sel ? b2 : b1;
    const float* Wsrc = sel ? Wk : Wq;
    const float* bsrc = sel ? bk : bq;
    float* Wout = sel ? g_Wfk : g_Wfq;
    float* bout = sel ? g_bfk : g_bfq;
    __shared__ float Ws[DD][DD + 1];
    __shared__ float Ts[DD][DD + 1];
    int tid = threadIdx.x;
    for (int t = tid; t < DD * DD; t += 256) {
        Ws[t >> 6][t & 63] = Wh[t];
        Ts[t >> 6][t & 63] = Wsrc[(h * DD + (t >> 6)) * HIDN + c0 + (t & 63)];
    }
    __syncthreads();
    if (blockIdx.z == 0 && tid < DD) {
        float acc = bh_[tid];
        for (int j = 0; j < DD; j++) acc += Ws[tid][j] * bsrc[h * DD + j];
        bout[h * DD + tid] = acc;
    }
    int i = tid & 63;
    int g = tid >> 6;
#pragma unroll
    for (int cc = 0; cc < 16; cc++) {
        int c = g * 16 + cc;
        float acc = 0.f;
#pragma unroll 8
        for (int j = 0; j < DD; j++) acc = fmaf(Ws[i][j], Ts[j][c], acc);
        Wout[(h * DD + i) * HIDN + c0 + c] = acc;
    }
}

// ---------------- tf32 tensor-core GEMM: out = X @ W^T + bias ----------------
// 64x64 tile / block, 4 warps (2x2), each warp 32x32 via m16n8k8 fragments.
// mode 0: plain [m, HIDN]; mode 1: head-major [bh][l][d]; mode 2: [bh][d][l]
__global__ void __launch_bounds__(128) gemm_tc(
    const float* __restrict__ X0, const float* __restrict__ Wm0, const float* __restrict__ B0, float* __restrict__ O0, int md0,
    const float* __restrict__ X1, const float* __restrict__ Wm1, const float* __restrict__ B1, float* __restrict__ O1, int md1,
    const float* __restrict__ X2, const float* __restrict__ Wm2, const float* __restrict__ B2, float* __restrict__ O2, int md2)
{
    const int BK = 32;
    int z = blockIdx.z;
    const float* X  = z == 0 ? X0  : (z == 1 ? X1  : X2);
    const float* W  = z == 0 ? Wm0 : (z == 1 ? Wm1 : Wm2);
    const float* Bi = z == 0 ? B0  : (z == 1 ? B1  : B2);
    float*       O  = z == 0 ? O0  : (z == 1 ? O1  : O2);
    int        mode = z == 0 ? md0 : (z == 1 ? md1 : md2);

    __shared__ unsigned Xs[64][36];   // [m][k] tf32 bits, stride 36 -> conflict-free frags
    __shared__ unsigned Ws[64][36];   // [n][k]

    int tid = threadIdx.x;
    int lane = tid & 31;
    int warp = tid >> 5;              // 0..3
    int warp_m = (warp & 1) * 32;
    int warp_n = (warp >> 1) * 32;
    int gr = lane >> 2;               // groupID 0..7
    int tg = lane & 3;                // threadID_in_group 0..3
    int m0 = blockIdx.y * 64, n0 = blockIdx.x * 64;

    float acc[2][4][4];
#pragma unroll
    for (int mt = 0; mt < 2; mt++)
#pragma unroll
        for (int nt = 0; nt < 4; nt++)
#pragma unroll
            for (int i = 0; i < 4; i++) acc[mt][nt][i] = 0.f;

    for (int kk = 0; kk < HIDN; kk += BK) {
#pragma unroll
        for (int i = 0; i < 4; i++) {
            int idx = tid + i * 128;          // 0..511
            int r = idx >> 3, c4 = idx & 7;
            float4 vx = *(const float4*)&X[(m0 + r) * HIDN + kk + c4 * 4];
            float4 vw = *(const float4*)&W[(n0 + r) * HIDN + kk + c4 * 4];
            uint4 ux, uw;
            ux.x = f2tf32(vx.x); ux.y = f2tf32(vx.y); ux.z = f2tf32(vx.z); ux.w = f2tf32(vx.w);
            uw.x = f2tf32(vw.x); uw.y = f2tf32(vw.y); uw.z = f2tf32(vw.z); uw.w = f2tf32(vw.w);
            *(uint4*)&Xs[r][c4 * 4] = ux;
            *(uint4*)&Ws[r][c4 * 4] = uw;
        }
        __syncthreads();
#pragma unroll
        for (int k8 = 0; k8 < 4; k8++) {
            int kb = k8 * 8;
            unsigned a[2][4], b[4][2];
#pragma unroll
            for (int mt = 0; mt < 2; mt++) {
                int rm = warp_m + mt * 16 + gr;
                a[mt][0] = Xs[rm    ][kb + tg];
                a[mt][1] = Xs[rm + 8][kb + tg];
                a[mt][2] = Xs[rm    ][kb + tg + 4];
                a[mt][3] = Xs[rm + 8][kb + tg + 4];
            }
#pragma unroll
            for (int nt = 0; nt < 4; nt++) {
                int rn = warp_n + nt * 8 + gr;
                b[nt][0] = Ws[rn][kb + tg];
                b[nt][1] = Ws[rn][kb + tg + 4];
            }
#pragma unroll
            for (int mt = 0; mt < 2; mt++)
#pragma unroll
                for (int nt = 0; nt < 4; nt++)
                    mma_tf32(acc[mt][nt], a[mt], b[nt]);
        }
        __syncthreads();
    }

    // epilogue
#pragma unroll
    for (int mt = 0; mt < 2; mt++) {
#pragma unroll
        for (int nt = 0; nt < 4; nt++) {
#pragma unroll
            for (int i = 0; i < 4; i++) {
                int row = warp_m + mt * 16 + gr + ((i >> 1) ? 8 : 0);
                int col = warp_n + nt * 8 + 2 * tg + (i & 1);
                int m = m0 + row, n = n0 + col;
                int b_ = m / LL, l = m - b_ * LL;
                float v = acc[mt][nt][i] + __ldg(&Bi[n]);
                if (mode == 0) {
                    O[m * HIDN + n] = v;
                } else if (mode == 1) {
                    int h = n >> 6, d = n & 63;
                    O[((b_ * HH + h) * LL + l) * DD + d] = v;
                } else {
                    int h = n >> 6, d = n & 63;
                    O[(b_ * HH + h) * DD * LL + d * LL + l] = v;
                }
            }
        }
    }
}

// ---------------- energy + softmax + AV, fully fused ----------------
__global__ void __launch_bounds__(256) energy_softmax_av(
    const int* __restrict__ mask, const float* __restrict__ vw,
    float* __restrict__ attn)
{
    __shared__ float   sQ[16][DD + 1];
    __shared__ __half2 sKh[DD][33];
    __shared__ float   sE[16][LL + 1];
    __shared__ __half2 sVW[DD];
    __shared__ float   sV[DD][DD];
    int tx = threadIdx.x, ty = threadIdx.y;  // (16,16)
    int tid = ty * 16 + tx;
    int bh = blockIdx.y, b = bh >> 3, h = bh & 7;
    int q0 = blockIdx.x * 16;
    if (tid < DD) sVW[tid] = __float2half2_rn(vw[tid]);
#pragma unroll
    for (int i = 0; i < 4; i++) {
        int idx = tid + i * 256;
        sQ[idx >> 6][idx & 63] = g_tQ[(bh * LL + q0) * DD + idx];
    }
    __syncthreads();
    const float* tKT = g_tKT + bh * DD * LL;
    for (int kc = 0; kc < LL; kc += DD) {
#pragma unroll
        for (int i = 0; i < 8; i++) {
            int idx = tid + i * 256;            // 0..2047
            int d = idx >> 5, p = idx & 31;
            float2 kv = *(const float2*)&tKT[d * LL + kc + p * 2];
            sKh[d][p] = __floats2half2_rn(kv.x, kv.y);
        }
        __syncthreads();
        __half2 acc0 = __floats2half2_rn(0.f, 0.f), acc1 = acc0;
#pragma unroll
        for (int d = 0; d < DD; d++) {
            __half2 q2 = __float2half2_rn(sQ[ty][d]);
            __half2 w2 = sVW[d];
            acc0 = __hfma2(w2, ath_h2tanh(__hadd2(q2, sKh[d][2 * tx])), acc0);
            acc1 = __hfma2(w2, ath_h2tanh(__hadd2(q2, sKh[d][2 * tx + 1])), acc1);
        }
        float2 e0 = __half22float2(acc0);
        float2 e1 = __half22float2(acc1);
        sE[ty][kc + 4 * tx + 0] = e0.x;
        sE[ty][kc + 4 * tx + 1] = e0.y;
        sE[ty][kc + 4 * tx + 2] = e1.x;
        sE[ty][kc + 4 * tx + 3] = e1.y;
        __syncthreads();
    }
    float ev[24];
    float mx = -3.0e38f;
#pragma unroll
    for (int i = 0; i < 24; i++) {
        int j = tx + i * 16;
        float e = sE[ty][j];
        if (__ldg(&mask[b * LL + j]) == 0) e = -1e10f;
        ev[i] = e;
        mx = fmaxf(mx, e);
    }
#pragma unroll
    for (int o = 8; o > 0; o >>= 1) mx = fmaxf(mx, __shfl_xor_sync(0xffffffffu, mx, o));
    float sum = 0.f;
#pragma unroll
    for (int i = 0; i < 24; i++) { ev[i] = __expf(ev[i] - mx); sum += ev[i]; }
#pragma unroll
    for (int o = 8; o > 0; o >>= 1) sum += __shfl_xor_sync(0xffffffffu, sum, o);
    float inv = __frcp_rn(sum);
#pragma unroll
    for (int i = 0; i < 24; i++) sE[ty][tx + i * 16] = ev[i] * inv;
    __syncthreads();
    float* dst = attn + (bh * LL + q0) * LL;
    for (int idx = tid; idx < 16 * LL; idx += 256) {
        int r = idx / LL, j = idx - r * LL;
        dst[r * LL + j] = sE[r][j];
    }
    // ---- AV: x_tile[16][64] = sE(16x384) @ V(384x64) ----
    float acc[4] = {0.f, 0.f, 0.f, 0.f};
    const float* Vb = g_V + bh * LL * DD;
    for (int kc = 0; kc < LL; kc += DD) {
        __syncthreads();
#pragma unroll
        for (int i = 0; i < 4; i++) {
            int idx = tid + i * 256;
            int r = idx >> 4, c4 = idx & 15;
            *(float4*)&sV[r][c4 * 4] = *(const float4*)&Vb[(kc + r) * DD + c4 * 4];
        }
        __syncthreads();
#pragma unroll 4
        for (int k = 0; k < DD; k++) {
            float a = sE[ty][kc + k];
            float4 v = *(const float4*)&sV[k][tx * 4];
            acc[0] = fmaf(a, v.x, acc[0]);
            acc[1] = fmaf(a, v.y, acc[1]);
            acc[2] = fmaf(a, v.z, acc[2]);
            acc[3] = fmaf(a, v.w, acc[3]);
        }
    }
    int q = q0 + ty;
    float4 xo; xo.x = acc[0]; xo.y = acc[1]; xo.z = acc[2]; xo.w = acc[3];
    *(float4*)&g_X[(b * LL + q) * HIDN + h * DD + tx * 4] = xo;
}

extern "C" void kernel_launch(void* const* d_in, const int* in_sizes, int n_in,
                              void* d_out, int out_size)
{
    const float* query = (const float*)d_in[0];
    const float* key_  = (const float*)d_in[1];
    const float* value = (const float*)d_in[2];
    const int*   mask  = (const int*)  d_in[3];
    const float* Wq = (const float*)d_in[4];
    const float* bq = (const float*)d_in[5];
    const float* Wk = (const float*)d_in[6];
    const float* bk = (const float*)d_in[7];
    const float* Wv = (const float*)d_in[8];
    const float* bv = (const float*)d_in[9];
    const float* Wo = (const float*)d_in[10];
    const float* bo = (const float*)d_in[11];
    const float* W1 = (const float*)d_in[12];
    const float* b1 = (const float*)d_in[13];
    const float* W2 = (const float*)d_in[14];
    const float* b2 = (const float*)d_in[15];
    const float* vw = (const float*)d_in[16];
    (void)d_in[17]; // vb cancels in softmax; raw energy never output
    (void)in_sizes; (void)n_in;

    float* out = (float*)d_out;

    float *gtQ, *gtKT, *gV, *gX, *gA, *gWfq, *gWfk, *gbfq, *gbfk;
    cudaGetSymbolAddress((void**)&gtQ,  g_tQ);
    cudaGetSymbolAddress((void**)&gtKT, g_tKT);
    cudaGetSymbolAddress((void**)&gV,   g_V);
    cudaGetSymbolAddress((void**)&gX,   g_X);
    cudaGetSymbolAddress((void**)&gA,   g_attn);
    cudaGetSymbolAddress((void**)&gWfq, g_Wfq);
    cudaGetSymbolAddress((void**)&gWfk, g_Wfk);
    cudaGetSymbolAddress((void**)&gbfq, g_bfq);
    cudaGetSymbolAddress((void**)&gbfk, g_bfk);

    float* attn_dst = (out_size >= X_ELEMS + A_ELEMS) ? (out + X_ELEMS) : gA;

    // 1) fuse W1@Wq and W2@Wk (128 blocks)
    prep_fuse<<<dim3(HH, 2, HIDN / 64), 256>>>(W1, b1, W2, b2, Wq, bq, Wk, bk);

    // 2) fused tQ / tK^T / V projection — tf32 tensor cores, 288 blocks
    gemm_tc<<<dim3(HIDN / 64, MROWS / 64, 3), 128>>>(
        query, gWfq, gbfq, gtQ,  1,
        key_,  gWfk, gbfk, gtKT, 2,
        value, Wv,   bv,   gV,   1);

    // 3) energy + softmax + AV fused (384 blocks)
    energy_softmax_av<<<dim3(LL / 16, BH), dim3(16, 16)>>>(mask, vw, attn_dst);

    // 4) output projection — tf32 tensor cores (96 blocks)
    gemm_tc<<<dim3(HIDN / 64, MROWS / 64, 1), 128>>>(
        gX, Wo, bo, out, 0,
        gX, Wo, bo, out, 0,
        gX, Wo, bo, out, 0);
}

// round 7
// speedup vs baseline: 2.6077x; 1.3043x over previous
#include <cuda_runtime.h>
#include <cuda_fp16.h>

#define BB 2
#define LL 384
#define HH 8
#define DD 64
#define HIDN 512
#define BH (BB*HH)          // 16
#define MROWS (BB*LL)       // 768
#define X_ELEMS (MROWS*HIDN)    // 393216
#define A_ELEMS (BH*LL*LL)      // 2359296

// -------- scratch (no dynamic allocation allowed) --------
__device__ float g_tQ [BH*LL*DD];   // [bh][l][d]
__device__ float g_tKT[BH*DD*LL];   // [bh][d][k]
__device__ float g_V  [BH*LL*DD];   // [bh][l][d]
__device__ float g_X  [X_ELEMS];
__device__ float g_attn[A_ELEMS];
__device__ float g_Wfq[HIDN*HIDN];
__device__ float g_Wfk[HIDN*HIDN];
__device__ float g_bfq[HIDN];
__device__ float g_bfk[HIDN];

__device__ __forceinline__ __half2 ath_h2tanh(__half2 x) {
    unsigned xi = *(unsigned*)&x, yi;
    asm("tanh.approx.f16x2 %0, %1;" : "=r"(yi) : "r"(xi));
    return *(__half2*)&yi;
}
__device__ __forceinline__ unsigned f2tf32(float f) {
    unsigned u;
    asm("cvt.rna.tf32.f32 %0, %1;" : "=r"(u) : "f"(f));
    return u;
}
__device__ __forceinline__ void mma_tf32(float* c, const unsigned* a, const unsigned* b) {
    asm volatile(
        "mma.sync.aligned.m16n8k8.row.col.f32.tf32.tf32.f32 "
        "{%0,%1,%2,%3}, {%4,%5,%6,%7}, {%8,%9}, {%0,%1,%2,%3};"
        : "+f"(c[0]), "+f"(c[1]), "+f"(c[2]), "+f"(c[3])
        : "r"(a[0]), "r"(a[1]), "r"(a[2]), "r"(a[3]), "r"(b[0]), "r"(b[1]));
}

// ---------------- prep: fused per-head weights ----------------
__global__ void __launch_bounds__(256) prep_fuse(
    const float* __restrict__ W1, const float* __restrict__ b1,
    const float* __restrict__ W2, const float* __restrict__ b2,
    const float* __restrict__ Wq, const float* __restrict__ bq,
    const float* __restrict__ Wk, const float* __restrict__ bk)
{
    int h   = blockIdx.x;
    int sel = blockIdx.y;
    int c0  = blockIdx.z * 64;
    const float* Wh   = sel ? W2 : W1;
    const float* bh_  = sel ? b2 : b1;
    const float* Wsrc = sel ? Wk : Wq;
    const float* bsrc = sel ? bk : bq;
    float* Wout = sel ? g_Wfk : g_Wfq;
    float* bout = sel ? g_bfk : g_bfq;
    __shared__ float Ws[DD][DD + 1];
    __shared__ float Ts[DD][DD + 1];
    int tid = threadIdx.x;
    for (int t = tid; t < DD * DD; t += 256) {
        Ws[t >> 6][t & 63] = Wh[t];
        Ts[t >> 6][t & 63] = Wsrc[(h * DD + (t >> 6)) * HIDN + c0 + (t & 63)];
    }
    __syncthreads();
    if (blockIdx.z == 0 && tid < DD) {
        float acc = bh_[tid];
        for (int j = 0; j < DD; j++) acc += Ws[tid][j] * bsrc[h * DD + j];
        bout[h * DD + tid] = acc;
    }
    int i = tid & 63;
    int g = tid >> 6;
#pragma unroll
    for (int cc = 0; cc < 16; cc++) {
        int c = g * 16 + cc;
        float acc = 0.f;
#pragma unroll 8
        for (int j = 0; j < DD; j++) acc = fmaf(Ws[i][j], Ts[j][c], acc);
        Wout[(h * DD + i) * HIDN + c0 + c] = acc;
    }
}

// ---------------- tf32 tensor-core GEMM v2: out = X @ W^T + bias ----------------
// 64x64 tile, 256 threads / 8 warps (4m x 2n), each warp 16x32.
// Register-prefetch pipeline; epilogue through smem -> coalesced float4 stores.
// mode 0: plain [m, HIDN]; mode 1: head-major [bh][l][d]; mode 2: [bh][d][l]
__global__ void __launch_bounds__(256) gemm_tc(
    const float* __restrict__ X0, const float* __restrict__ Wm0, const float* __restrict__ B0, float* __restrict__ O0, int md0,
    const float* __restrict__ X1, const float* __restrict__ Wm1, const float* __restrict__ B1, float* __restrict__ O1, int md1,
    const float* __restrict__ X2, const float* __restrict__ Wm2, const float* __restrict__ B2, float* __restrict__ O2, int md2)
{
    const int BK = 32;
    int z = blockIdx.z;
    const float* X  = z == 0 ? X0  : (z == 1 ? X1  : X2);
    const float* W  = z == 0 ? Wm0 : (z == 1 ? Wm1 : Wm2);
    const float* Bi = z == 0 ? B0  : (z == 1 ? B1  : B2);
    float*       O  = z == 0 ? O0  : (z == 1 ? O1  : O2);
    int        mode = z == 0 ? md0 : (z == 1 ? md1 : md2);

    // out stride 68 (multiple of 4) keeps every float4 access 16B-aligned
    __shared__ union {
        struct { unsigned X[64][36]; unsigned W[64][36]; } st;  // 18432 B
        float out[64][68];                                      // 17408 B
    } sm;

    int tid = threadIdx.x;
    int lane = tid & 31;
    int warp = tid >> 5;              // 0..7
    int warp_m = (warp & 3) * 16;
    int warp_n = (warp >> 2) * 32;
    int gr = lane >> 2;               // 0..7
    int tg = lane & 3;                // 0..3
    int m0 = blockIdx.y * 64, n0 = blockIdx.x * 64;

    int ldr  = tid >> 3;              // 0..31 load row
    int ldc4 = tid & 7;               // 0..7 float4 col

    float acc[4][4];
#pragma unroll
    for (int nt = 0; nt < 4; nt++)
#pragma unroll
        for (int i = 0; i < 4; i++) acc[nt][i] = 0.f;

    // prefetch tile 0
    float4 px[2], pw[2];
#pragma unroll
    for (int i = 0; i < 2; i++) {
        int r = ldr + i * 32;
        px[i] = *(const float4*)&X[(m0 + r) * HIDN + ldc4 * 4];
        pw[i] = *(const float4*)&W[(n0 + r) * HIDN + ldc4 * 4];
    }

    for (int kk = 0; kk < HIDN; kk += BK) {
        // stage prefetched tile (fp32 -> tf32)
#pragma unroll
        for (int i = 0; i < 2; i++) {
            int r = ldr + i * 32;
            uint4 ux, uw;
            ux.x = f2tf32(px[i].x); ux.y = f2tf32(px[i].y); ux.z = f2tf32(px[i].z); ux.w = f2tf32(px[i].w);
            uw.x = f2tf32(pw[i].x); uw.y = f2tf32(pw[i].y); uw.z = f2tf32(pw[i].z); uw.w = f2tf32(pw[i].w);
            *(uint4*)&sm.st.X[r][ldc4 * 4] = ux;
            *(uint4*)&sm.st.W[r][ldc4 * 4] = uw;
        }
        __syncthreads();
        // prefetch next tile while MMAs run
        if (kk + BK < HIDN) {
#pragma unroll
            for (int i = 0; i < 2; i++) {
                int r = ldr + i * 32;
                px[i] = *(const float4*)&X[(m0 + r) * HIDN + kk + BK + ldc4 * 4];
                pw[i] = *(const float4*)&W[(n0 + r) * HIDN + kk + BK + ldc4 * 4];
            }
        }
#pragma unroll
        for (int k8 = 0; k8 < 4; k8++) {
            int kb = k8 * 8;
            unsigned a[4], b[4][2];
            a[0] = sm.st.X[warp_m + gr    ][kb + tg];
            a[1] = sm.st.X[warp_m + gr + 8][kb + tg];
            a[2] = sm.st.X[warp_m + gr    ][kb + tg + 4];
            a[3] = sm.st.X[warp_m + gr + 8][kb + tg + 4];
#pragma unroll
            for (int nt = 0; nt < 4; nt++) {
                int rn = warp_n + nt * 8 + gr;
                b[nt][0] = sm.st.W[rn][kb + tg];
                b[nt][1] = sm.st.W[rn][kb + tg + 4];
            }
#pragma unroll
            for (int nt = 0; nt < 4; nt++)
                mma_tf32(acc[nt], a, b[nt]);
        }
        __syncthreads();
    }

    // epilogue: acc -> smem tile (overlays staging buffers; all reads done)
#pragma unroll
    for (int nt = 0; nt < 4; nt++) {
        int col = warp_n + nt * 8 + 2 * tg;
        sm.out[warp_m + gr    ][col    ] = acc[nt][0];
        sm.out[warp_m + gr    ][col + 1] = acc[nt][1];
        sm.out[warp_m + gr + 8][col    ] = acc[nt][2];
        sm.out[warp_m + gr + 8][col + 1] = acc[nt][3];
    }
    __syncthreads();

    if (mode != 2) {
#pragma unroll
        for (int i = 0; i < 4; i++) {
            int idx = tid + i * 256;         // 0..1023
            int r = idx >> 4, c4 = idx & 15;
            float4 v = *(float4*)&sm.out[r][c4 * 4];
            float4 b4 = *(const float4*)&Bi[n0 + c4 * 4];
            v.x += b4.x; v.y += b4.y; v.z += b4.z; v.w += b4.w;
            int m = m0 + r;
            int b_ = m / LL, l = m - b_ * LL;
            if (mode == 0) {
                *(float4*)&O[m * HIDN + n0 + c4 * 4] = v;
            } else {
                int h = n0 >> 6;
                *(float4*)&O[((b_ * HH + h) * LL + l) * DD + c4 * 4] = v;
            }
        }
    } else {
        // [bh][d][l], coalesced along l (all 64 m-rows share one batch: 64 | LL)
        int b_ = m0 / LL, l0 = m0 - b_ * LL;
        int h = n0 >> 6;
        float* base = O + (b_ * HH + h) * DD * LL;
#pragma unroll
        for (int i = 0; i < 4; i++) {
            int idx = tid + i * 256;         // 0..1023
            int d = idx >> 4, l4 = idx & 15;
            float bd = __ldg(&Bi[n0 + d]);
            float4 v;
            v.x = sm.out[l4 * 4 + 0][d] + bd;
            v.y = sm.out[l4 * 4 + 1][d] + bd;
            v.z = sm.out[l4 * 4 + 2][d] + bd;
            v.w = sm.out[l4 * 4 + 3][d] + bd;
            *(float4*)&base[d * LL + l0 + l4 * 4] = v;
        }
    }
}

// ---------------- energy + softmax + AV, fully fused ----------------
__global__ void __launch_bounds__(256) energy_softmax_av(
    const int* __restrict__ mask, const float* __restrict__ vw,
    float* __restrict__ attn)
{
    __shared__ float   sQ[16][DD + 1];
    __shared__ __half2 sKh[DD][33];
    __shared__ float   sE[16][LL + 1];
    __shared__ __half2 sVW[DD];
    __shared__ float   sV[DD][DD];
    int tx = threadIdx.x, ty = threadIdx.y;  // (16,16)
    int tid = ty * 16 + tx;
    int bh = blockIdx.y, b = bh >> 3, h = bh & 7;
    int q0 = blockIdx.x * 16;
    if (tid < DD) sVW[tid] = __float2half2_rn(vw[tid]);
#pragma unroll
    for (int i = 0; i < 4; i++) {
        int idx = tid + i * 256;
        sQ[idx >> 6][idx & 63] = g_tQ[(bh * LL + q0) * DD + idx];
    }
    __syncthreads();
    const float* tKT = g_tKT + bh * DD * LL;
    for (int kc = 0; kc < LL; kc += DD) {
#pragma unroll
        for (int i = 0; i < 8; i++) {
            int idx = tid + i * 256;            // 0..2047
            int d = idx >> 5, p = idx & 31;
            float2 kv = *(const float2*)&tKT[d * LL + kc + p * 2];
            sKh[d][p] = __floats2half2_rn(kv.x, kv.y);
        }
        __syncthreads();
        __half2 acc0 = __floats2half2_rn(0.f, 0.f), acc1 = acc0;
#pragma unroll
        for (int d = 0; d < DD; d++) {
            __half2 q2 = __float2half2_rn(sQ[ty][d]);
            __half2 w2 = sVW[d];
            acc0 = __hfma2(w2, ath_h2tanh(__hadd2(q2, sKh[d][2 * tx])), acc0);
            acc1 = __hfma2(w2, ath_h2tanh(__hadd2(q2, sKh[d][2 * tx + 1])), acc1);
        }
        float2 e0 = __half22float2(acc0);
        float2 e1 = __half22float2(acc1);
        sE[ty][kc + 4 * tx + 0] = e0.x;
        sE[ty][kc + 4 * tx + 1] = e0.y;
        sE[ty][kc + 4 * tx + 2] = e1.x;
        sE[ty][kc + 4 * tx + 3] = e1.y;
        __syncthreads();
    }
    float ev[24];
    float mx = -3.0e38f;
#pragma unroll
    for (int i = 0; i < 24; i++) {
        int j = tx + i * 16;
        float e = sE[ty][j];
        if (__ldg(&mask[b * LL + j]) == 0) e = -1e10f;
        ev[i] = e;
        mx = fmaxf(mx, e);
    }
#pragma unroll
    for (int o = 8; o > 0; o >>= 1) mx = fmaxf(mx, __shfl_xor_sync(0xffffffffu, mx, o));
    float sum = 0.f;
#pragma unroll
    for (int i = 0; i < 24; i++) { ev[i] = __expf(ev[i] - mx); sum += ev[i]; }
#pragma unroll
    for (int o = 8; o > 0; o >>= 1) sum += __shfl_xor_sync(0xffffffffu, sum, o);
    float inv = __frcp_rn(sum);
#pragma unroll
    for (int i = 0; i < 24; i++) sE[ty][tx + i * 16] = ev[i] * inv;
    __syncthreads();
    float* dst = attn + (bh * LL + q0) * LL;
    for (int idx = tid; idx < 16 * LL; idx += 256) {
        int r = idx / LL, j = idx - r * LL;
        dst[r * LL + j] = sE[r][j];
    }
    // ---- AV: x_tile[16][64] = sE(16x384) @ V(384x64) ----
    float acc[4] = {0.f, 0.f, 0.f, 0.f};
    const float* Vb = g_V + bh * LL * DD;
    for (int kc = 0; kc < LL; kc += DD) {
        __syncthreads();
#pragma unroll
        for (int i = 0; i < 4; i++) {
            int idx = tid + i * 256;
            int r = idx >> 4, c4 = idx & 15;
            *(float4*)&sV[r][c4 * 4] = *(const float4*)&Vb[(kc + r) * DD + c4 * 4];
        }
        __syncthreads();
#pragma unroll 4
        for (int k = 0; k < DD; k++) {
            float a = sE[ty][kc + k];
            float4 v = *(const float4*)&sV[k][tx * 4];
            acc[0] = fmaf(a, v.x, acc[0]);
            acc[1] = fmaf(a, v.y, acc[1]);
            acc[2] = fmaf(a, v.z, acc[2]);
            acc[3] = fmaf(a, v.w, acc[3]);
        }
    }
    int q = q0 + ty;
    float4 xo; xo.x = acc[0]; xo.y = acc[1]; xo.z = acc[2]; xo.w = acc[3];
    *(float4*)&g_X[(b * LL + q) * HIDN + h * DD + tx * 4] = xo;
}

extern "C" void kernel_launch(void* const* d_in, const int* in_sizes, int n_in,
                              void* d_out, int out_size)
{
    const float* query = (const float*)d_in[0];
    const float* key_  = (const float*)d_in[1];
    const float* value = (const float*)d_in[2];
    const int*   mask  = (const int*)  d_in[3];
    const float* Wq = (const float*)d_in[4];
    const float* bq = (const float*)d_in[5];
    const float* Wk = (const float*)d_in[6];
    const float* bk = (const float*)d_in[7];
    const float* Wv = (const float*)d_in[8];
    const float* bv = (const float*)d_in[9];
    const float* Wo = (const float*)d_in[10];
    const float* bo = (const float*)d_in[11];
    const float* W1 = (const float*)d_in[12];
    const float* b1 = (const float*)d_in[13];
    const float* W2 = (const float*)d_in[14];
    const float* b2 = (const float*)d_in[15];
    const float* vw = (const float*)d_in[16];
    (void)d_in[17]; // vb cancels in softmax; raw energy never output
    (void)in_sizes; (void)n_in;

    float* out = (float*)d_out;

    float *gtQ, *gtKT, *gV, *gX, *gA, *gWfq, *gWfk, *gbfq, *gbfk;
    cudaGetSymbolAddress((void**)&gtQ,  g_tQ);
    cudaGetSymbolAddress((void**)&gtKT, g_tKT);
    cudaGetSymbolAddress((void**)&gV,   g_V);
    cudaGetSymbolAddress((void**)&gX,   g_X);
    cudaGetSymbolAddress((void**)&gA,   g_attn);
    cudaGetSymbolAddress((void**)&gWfq, g_Wfq);
    cudaGetSymbolAddress((void**)&gWfk, g_Wfk);
    cudaGetSymbolAddress((void**)&gbfq, g_bfq);
    cudaGetSymbolAddress((void**)&gbfk, g_bfk);

    float* attn_dst = (out_size >= X_ELEMS + A_ELEMS) ? (out + X_ELEMS) : gA;

    // 1) fuse W1@Wq and W2@Wk (128 blocks)
    prep_fuse<<<dim3(HH, 2, HIDN / 64), 256>>>(W1, b1, W2, b2, Wq, bq, Wk, bk);

    // 2) fused tQ / tK^T / V projection — tf32 TC, 288 blocks x 256 thr
    gemm_tc<<<dim3(HIDN / 64, MROWS / 64, 3), 256>>>(
        query, gWfq, gbfq, gtQ,  1,
        key_,  gWfk, gbfk, gtKT, 2,
        value, Wv,   bv,   gV,   1);

    // 3) energy + softmax + AV fused (384 blocks)
    energy_softmax_av<<<dim3(LL / 16, BH), dim3(16, 16)>>>(mask, vw, attn_dst);

    // 4) output projection — tf32 TC (96 blocks x 256 thr)
    gemm_tc<<<dim3(HIDN / 64, MROWS / 64, 1), 256>>>(
        gX, Wo, bo, out, 0,
        gX, Wo, bo, out, 0,
        gX, Wo, bo, out, 0);
}

// round 8
// speedup vs baseline: 2.6428x; 1.0135x over previous
#include <cuda_runtime.h>
#include <cuda_fp16.h>

#define BB 2
#define LL 384
#define HH 8
#define DD 64
#define HIDN 512
#define BH (BB*HH)          // 16
#define MROWS (BB*LL)       // 768
#define X_ELEMS (MROWS*HIDN)    // 393216
#define A_ELEMS (BH*LL*LL)      // 2359296

// -------- scratch (no dynamic allocation allowed) --------
__device__ float g_tQ [BH*LL*DD];   // [bh][l][d]
__device__ float g_tKT[BH*DD*LL];   // [bh][d][k]
__device__ float g_V  [BH*LL*DD];   // [bh][l][d]
__device__ float g_X  [X_ELEMS];
__device__ float g_attn[A_ELEMS];
__device__ float g_Wfq[HIDN*HIDN];
__device__ float g_Wfk[HIDN*HIDN];
__device__ float g_bfq[HIDN];
__device__ float g_bfk[HIDN];

__device__ __forceinline__ __half2 ath_h2tanh(__half2 x) {
    unsigned xi = *(unsigned*)&x, yi;
    asm("tanh.approx.f16x2 %0, %1;" : "=r"(yi) : "r"(xi));
    return *(__half2*)&yi;
}
__device__ __forceinline__ unsigned f2tf32(float f) {
    unsigned u;
    asm("cvt.rna.tf32.f32 %0, %1;" : "=r"(u) : "f"(f));
    return u;
}
__device__ __forceinline__ void mma_tf32(float* c, const unsigned* a, const unsigned* b) {
    asm volatile(
        "mma.sync.aligned.m16n8k8.row.col.f32.tf32.tf32.f32 "
        "{%0,%1,%2,%3}, {%4,%5,%6,%7}, {%8,%9}, {%0,%1,%2,%3};"
        : "+f"(c[0]), "+f"(c[1]), "+f"(c[2]), "+f"(c[3])
        : "r"(a[0]), "r"(a[1]), "r"(a[2]), "r"(a[3]), "r"(b[0]), "r"(b[1]));
}

// ---------------- prep: fused per-head weights ----------------
__global__ void __launch_bounds__(256) prep_fuse(
    const float* __restrict__ W1, const float* __restrict__ b1,
    const float* __restrict__ W2, const float* __restrict__ b2,
    const float* __restrict__ Wq, const float* __restrict__ bq,
    const float* __restrict__ Wk, const float* __restrict__ bk)
{
    int h   = blockIdx.x;
    int sel = blockIdx.y;
    int c0  = blockIdx.z * 64;
    const float* Wh   = sel ? W2 : W1;
    const float* bh_  = sel ? b2 : b1;
    const float* Wsrc = sel ? Wk : Wq;
    const float* bsrc = sel ? bk : bq;
    float* Wout = sel ? g_Wfk : g_Wfq;
    float* bout = sel ? g_bfk : g_bfq;
    __shared__ float Ws[DD][DD + 1];
    __shared__ float Ts[DD][DD + 1];
    int tid = threadIdx.x;
    for (int t = tid; t < DD * DD; t += 256) {
        Ws[t >> 6][t & 63] = Wh[t];
        Ts[t >> 6][t & 63] = Wsrc[(h * DD + (t >> 6)) * HIDN + c0 + (t & 63)];
    }
    __syncthreads();
    if (blockIdx.z == 0 && tid < DD) {
        float acc = bh_[tid];
        for (int j = 0; j < DD; j++) acc += Ws[tid][j] * bsrc[h * DD + j];
        bout[h * DD + tid] = acc;
    }
    int i = tid & 63;
    int g = tid >> 6;
#pragma unroll
    for (int cc = 0; cc < 16; cc++) {
        int c = g * 16 + cc;
        float acc = 0.f;
#pragma unroll 8
        for (int j = 0; j < DD; j++) acc = fmaf(Ws[i][j], Ts[j][c], acc);
        Wout[(h * DD + i) * HIDN + c0 + c] = acc;
    }
}

// ---------------- tf32 tensor-core GEMM: out = X @ W^T + bias ----------------
__global__ void __launch_bounds__(256) gemm_tc(
    const float* __restrict__ X0, const float* __restrict__ Wm0, const float* __restrict__ B0, float* __restrict__ O0, int md0,
    const float* __restrict__ X1, const float* __restrict__ Wm1, const float* __restrict__ B1, float* __restrict__ O1, int md1,
    const float* __restrict__ X2, const float* __restrict__ Wm2, const float* __restrict__ B2, float* __restrict__ O2, int md2)
{
    const int BK = 32;
    int z = blockIdx.z;
    const float* X  = z == 0 ? X0  : (z == 1 ? X1  : X2);
    const float* W  = z == 0 ? Wm0 : (z == 1 ? Wm1 : Wm2);
    const float* Bi = z == 0 ? B0  : (z == 1 ? B1  : B2);
    float*       O  = z == 0 ? O0  : (z == 1 ? O1  : O2);
    int        mode = z == 0 ? md0 : (z == 1 ? md1 : md2);

    __shared__ union {
        struct { unsigned X[64][36]; unsigned W[64][36]; } st;  // 18432 B
        float out[64][68];                                      // 17408 B
    } sm;

    int tid = threadIdx.x;
    int lane = tid & 31;
    int warp = tid >> 5;
    int warp_m = (warp & 3) * 16;
    int warp_n = (warp >> 2) * 32;
    int gr = lane >> 2;
    int tg = lane & 3;
    int m0 = blockIdx.y * 64, n0 = blockIdx.x * 64;

    int ldr  = tid >> 3;
    int ldc4 = tid & 7;

    float acc[4][4];
#pragma unroll
    for (int nt = 0; nt < 4; nt++)
#pragma unroll
        for (int i = 0; i < 4; i++) acc[nt][i] = 0.f;

    float4 px[2], pw[2];
#pragma unroll
    for (int i = 0; i < 2; i++) {
        int r = ldr + i * 32;
        px[i] = *(const float4*)&X[(m0 + r) * HIDN + ldc4 * 4];
        pw[i] = *(const float4*)&W[(n0 + r) * HIDN + ldc4 * 4];
    }

    for (int kk = 0; kk < HIDN; kk += BK) {
#pragma unroll
        for (int i = 0; i < 2; i++) {
            int r = ldr + i * 32;
            uint4 ux, uw;
            ux.x = f2tf32(px[i].x); ux.y = f2tf32(px[i].y); ux.z = f2tf32(px[i].z); ux.w = f2tf32(px[i].w);
            uw.x = f2tf32(pw[i].x); uw.y = f2tf32(pw[i].y); uw.z = f2tf32(pw[i].z); uw.w = f2tf32(pw[i].w);
            *(uint4*)&sm.st.X[r][ldc4 * 4] = ux;
            *(uint4*)&sm.st.W[r][ldc4 * 4] = uw;
        }
        __syncthreads();
        if (kk + BK < HIDN) {
#pragma unroll
            for (int i = 0; i < 2; i++) {
                int r = ldr + i * 32;
                px[i] = *(const float4*)&X[(m0 + r) * HIDN + kk + BK + ldc4 * 4];
                pw[i] = *(const float4*)&W[(n0 + r) * HIDN + kk + BK + ldc4 * 4];
            }
        }
#pragma unroll
        for (int k8 = 0; k8 < 4; k8++) {
            int kb = k8 * 8;
            unsigned a[4], b[4][2];
            a[0] = sm.st.X[warp_m + gr    ][kb + tg];
            a[1] = sm.st.X[warp_m + gr + 8][kb + tg];
            a[2] = sm.st.X[warp_m + gr    ][kb + tg + 4];
            a[3] = sm.st.X[warp_m + gr + 8][kb + tg + 4];
#pragma unroll
            for (int nt = 0; nt < 4; nt++) {
                int rn = warp_n + nt * 8 + gr;
                b[nt][0] = sm.st.W[rn][kb + tg];
                b[nt][1] = sm.st.W[rn][kb + tg + 4];
            }
#pragma unroll
            for (int nt = 0; nt < 4; nt++)
                mma_tf32(acc[nt], a, b[nt]);
        }
        __syncthreads();
    }

#pragma unroll
    for (int nt = 0; nt < 4; nt++) {
        int col = warp_n + nt * 8 + 2 * tg;
        sm.out[warp_m + gr    ][col    ] = acc[nt][0];
        sm.out[warp_m + gr    ][col + 1] = acc[nt][1];
        sm.out[warp_m + gr + 8][col    ] = acc[nt][2];
        sm.out[warp_m + gr + 8][col + 1] = acc[nt][3];
    }
    __syncthreads();

    if (mode != 2) {
#pragma unroll
        for (int i = 0; i < 4; i++) {
            int idx = tid + i * 256;
            int r = idx >> 4, c4 = idx & 15;
            float4 v = *(float4*)&sm.out[r][c4 * 4];
            float4 b4 = *(const float4*)&Bi[n0 + c4 * 4];
            v.x += b4.x; v.y += b4.y; v.z += b4.z; v.w += b4.w;
            int m = m0 + r;
            int b_ = m / LL, l = m - b_ * LL;
            if (mode == 0) {
                *(float4*)&O[m * HIDN + n0 + c4 * 4] = v;
            } else {
                int h = n0 >> 6;
                *(float4*)&O[((b_ * HH + h) * LL + l) * DD + c4 * 4] = v;
            }
        }
    } else {
        int b_ = m0 / LL, l0 = m0 - b_ * LL;
        int h = n0 >> 6;
        float* base = O + (b_ * HH + h) * DD * LL;
#pragma unroll
        for (int i = 0; i < 4; i++) {
            int idx = tid + i * 256;
            int d = idx >> 4, l4 = idx & 15;
            float bd = __ldg(&Bi[n0 + d]);
            float4 v;
            v.x = sm.out[l4 * 4 + 0][d] + bd;
            v.y = sm.out[l4 * 4 + 1][d] + bd;
            v.z = sm.out[l4 * 4 + 2][d] + bd;
            v.w = sm.out[l4 * 4 + 3][d] + bd;
            *(float4*)&base[d * LL + l0 + l4 * 4] = v;
        }
    }
}

// ---------------- energy + softmax + AV, v2 (register softmax, MUFU-bound) ----------------
// block = 256 thr, tile = 16 q x 384 k of one (b,h).
// thread (ty=q, tx): 12 k-energies per k-chunk x 2 chunks = 24 energies in registers.
struct ESmem {
    union {
        __half2 Kh[DD][96];                              // phase 1: 24576 B (192 k as half2)
        struct { float E[16][LL + 2]; float V[DD][DD]; } p3;  // 24704 + 16384 B
    } u;
    __half2 Qh[16][DD];    // q duplicated into both halves
    __half2 VW[DD];
    int     M[LL];
};

__global__ void __launch_bounds__(256) energy_softmax_av(
    const int* __restrict__ mask, const float* __restrict__ vw,
    float* __restrict__ attn)
{
    __shared__ ESmem sm;
    int tid = threadIdx.x;
    int tx = tid & 15, ty = tid >> 4;
    int bh = blockIdx.y, b = bh >> 3, h = bh & 7;
    int q0 = blockIdx.x * 16;

    if (tid < DD) sm.VW[tid] = __float2half2_rn(vw[tid]);
    for (int j = tid; j < LL; j += 256) sm.M[j] = mask[b * LL + j];
    {
        const float* qsrc = g_tQ + (bh * LL + q0) * DD;
#pragma unroll
        for (int i = 0; i < 4; i++) {
            int idx = tid + i * 256;      // 0..1023 = 16q x 64d
            sm.Qh[idx >> 6][idx & 63] = __float2half2_rn(qsrc[idx]);
        }
    }

    const float* tKT = g_tKT + bh * DD * LL;
    __half2 acc[12];
#pragma unroll
    for (int i = 0; i < 12; i++) acc[i] = __floats2half2_rn(0.f, 0.f);

#pragma unroll
    for (int c = 0; c < 2; c++) {
        __syncthreads();
        // load K chunk: 64 d x 96 half2 (192 k), coalesced float2 reads
#pragma unroll
        for (int i = 0; i < 24; i++) {
            int idx = tid + i * 256;       // 0..6143
            int d = idx / 96, p = idx - d * 96;
            float2 kv = *(const float2*)&tKT[d * LL + c * 192 + p * 2];
            sm.u.Kh[d][p] = __floats2half2_rn(kv.x, kv.y);
        }
        __syncthreads();
#pragma unroll 4
        for (int d = 0; d < DD; d++) {
            __half2 q2 = sm.Qh[ty][d];
            __half2 w2 = sm.VW[d];
            uint2 k01 = *(const uint2*)&sm.u.Kh[d][tx * 6];
            uint2 k23 = *(const uint2*)&sm.u.Kh[d][tx * 6 + 2];
            uint2 k45 = *(const uint2*)&sm.u.Kh[d][tx * 6 + 4];
            __half2 kv[6];
            kv[0] = *(__half2*)&k01.x; kv[1] = *(__half2*)&k01.y;
            kv[2] = *(__half2*)&k23.x; kv[3] = *(__half2*)&k23.y;
            kv[4] = *(__half2*)&k45.x; kv[5] = *(__half2*)&k45.y;
#pragma unroll
            for (int jj = 0; jj < 6; jj++)
                acc[c * 6 + jj] = __hfma2(w2, ath_h2tanh(__hadd2(q2, kv[jj])), acc[c * 6 + jj]);
        }
    }

    // ---- softmax in registers (row ty across 16 tx lanes; lane = (ty&1)*16+tx) ----
    float ev[24];
    float mx = -3.0e38f;
#pragma unroll
    for (int a = 0; a < 12; a++) {
        int kb = (a >= 6 ? 192 : 0) + (tx * 6 + (a % 6)) * 2;
        float2 e = __half22float2(acc[a]);
        if (sm.M[kb]     == 0) e.x = -1e10f;
        if (sm.M[kb + 1] == 0) e.y = -1e10f;
        ev[2 * a] = e.x; ev[2 * a + 1] = e.y;
        mx = fmaxf(mx, fmaxf(e.x, e.y));
    }
#pragma unroll
    for (int o = 8; o > 0; o >>= 1) mx = fmaxf(mx, __shfl_xor_sync(0xffffffffu, mx, o));
    float sum = 0.f;
#pragma unroll
    for (int i = 0; i < 24; i++) { ev[i] = __expf(ev[i] - mx); sum += ev[i]; }
#pragma unroll
    for (int o = 8; o > 0; o >>= 1) sum += __shfl_xor_sync(0xffffffffu, sum, o);
    float inv = __frcp_rn(sum);

    __syncthreads();   // all Kh reads done -> safe to overlay with E/V
#pragma unroll
    for (int a = 0; a < 12; a++) {
        int k2 = (a >= 6 ? 96 : 0) + tx * 6 + (a % 6);
        float2 pr; pr.x = ev[2 * a] * inv; pr.y = ev[2 * a + 1] * inv;
        *(float2*)&sm.u.p3.E[ty][k2 * 2] = pr;
    }
    __syncthreads();

    // coalesced attn store
    float* dst = attn + (bh * LL + q0) * LL;
    for (int idx = tid; idx < 16 * LL; idx += 256) {
        int r = idx / LL, j = idx - r * LL;
        dst[r * LL + j] = sm.u.p3.E[r][j];
    }

    // ---- AV: x_tile[16][64] = E(16x384) @ V(384x64) ----
    float xacc[4] = {0.f, 0.f, 0.f, 0.f};
    const float* Vb = g_V + bh * LL * DD;
    for (int kc = 0; kc < LL; kc += DD) {
        __syncthreads();
#pragma unroll
        for (int i = 0; i < 4; i++) {
            int idx = tid + i * 256;
            int r = idx >> 4, c4 = idx & 15;
            *(float4*)&sm.u.p3.V[r][c4 * 4] = *(const float4*)&Vb[(kc + r) * DD + c4 * 4];
        }
        __syncthreads();
#pragma unroll 4
        for (int k = 0; k < DD; k++) {
            float a = sm.u.p3.E[ty][kc + k];
            float4 v = *(const float4*)&sm.u.p3.V[k][tx * 4];
            xacc[0] = fmaf(a, v.x, xacc[0]);
            xacc[1] = fmaf(a, v.y, xacc[1]);
            xacc[2] = fmaf(a, v.z, xacc[2]);
            xacc[3] = fmaf(a, v.w, xacc[3]);
        }
    }
    int q = q0 + ty;
    float4 xo; xo.x = xacc[0]; xo.y = xacc[1]; xo.z = xacc[2]; xo.w = xacc[3];
    *(float4*)&g_X[(b * LL + q) * HIDN + h * DD + tx * 4] = xo;
}

extern "C" void kernel_launch(void* const* d_in, const int* in_sizes, int n_in,
                              void* d_out, int out_size)
{
    const float* query = (const float*)d_in[0];
    const float* key_  = (const float*)d_in[1];
    const float* value = (const float*)d_in[2];
    const int*   mask  = (const int*)  d_in[3];
    const float* Wq = (const float*)d_in[4];
    const float* bq = (const float*)d_in[5];
    const float* Wk = (const float*)d_in[6];
    const float* bk = (const float*)d_in[7];
    const float* Wv = (const float*)d_in[8];
    const float* bv = (const float*)d_in[9];
    const float* Wo = (const float*)d_in[10];
    const float* bo = (const float*)d_in[11];
    const float* W1 = (const float*)d_in[12];
    const float* b1 = (const float*)d_in[13];
    const float* W2 = (const float*)d_in[14];
    const float* b2 = (const float*)d_in[15];
    const float* vw = (const float*)d_in[16];
    (void)d_in[17]; // vb cancels in softmax; raw energy never output
    (void)in_sizes; (void)n_in;

    float* out = (float*)d_out;

    float *gtQ, *gtKT, *gV, *gX, *gA, *gWfq, *gWfk, *gbfq, *gbfk;
    cudaGetSymbolAddress((void**)&gtQ,  g_tQ);
    cudaGetSymbolAddress((void**)&gtKT, g_tKT);
    cudaGetSymbolAddress((void**)&gV,   g_V);
    cudaGetSymbolAddress((void**)&gX,   g_X);
    cudaGetSymbolAddress((void**)&gA,   g_attn);
    cudaGetSymbolAddress((void**)&gWfq, g_Wfq);
    cudaGetSymbolAddress((void**)&gWfk, g_Wfk);
    cudaGetSymbolAddress((void**)&gbfq, g_bfq);
    cudaGetSymbolAddress((void**)&gbfk, g_bfk);

    float* attn_dst = (out_size >= X_ELEMS + A_ELEMS) ? (out + X_ELEMS) : gA;

    // 1) fuse W1@Wq and W2@Wk (128 blocks)
    prep_fuse<<<dim3(HH, 2, HIDN / 64), 256>>>(W1, b1, W2, b2, Wq, bq, Wk, bk);

    // 2) fused tQ / tK^T / V projection — tf32 TC, 288 blocks
    gemm_tc<<<dim3(HIDN / 64, MROWS / 64, 3), 256>>>(
        query, gWfq, gbfq, gtQ,  1,
        key_,  gWfk, gbfk, gtKT, 2,
        value, Wv,   bv,   gV,   1);

    // 3) energy + softmax + AV fused v2 (384 blocks)
    energy_softmax_av<<<dim3(LL / 16, BH), 256>>>(mask, vw, attn_dst);

    // 4) output projection — tf32 TC (96 blocks)
    gemm_tc<<<dim3(HIDN / 64, MROWS / 64, 1), 256>>>(
        gX, Wo, bo, out, 0,
        gX, Wo, bo, out, 0,
        gX, Wo, bo, out, 0);
}

// round 9
// speedup vs baseline: 3.6936x; 1.3976x over previous
#include <cuda_runtime.h>
#include <cuda_fp16.h>

#define BB 2
#define LL 384
#define HH 8
#define DD 64
#define HIDN 512
#define BH (BB*HH)          // 16
#define MROWS (BB*LL)       // 768
#define X_ELEMS (MROWS*HIDN)    // 393216
#define A_ELEMS (BH*LL*LL)      // 2359296
#define FD 256              // feature dim (4 segments x 64)

// -------- scratch (no dynamic allocation allowed) --------
__device__ __half g_FQ[BH*LL*FD];   // [bh][l][256]  q-side features
__device__ __half g_FK[BH*LL*FD];   // [bh][l][256]  k-side features
__device__ __half g_Vh[BH*DD*LL];   // [bh][d][l]    V transposed, half
__device__ float  g_ck[BH*LL];      // per-k energy constant
__device__ float  g_X [X_ELEMS];
__device__ float  g_attn[A_ELEMS];
__device__ float  g_Wfq[HIDN*HIDN];
__device__ float  g_Wfk[HIDN*HIDN];
__device__ float  g_bfq[HIDN];
__device__ float  g_bfk[HIDN];

__device__ __forceinline__ float tanh_ap(float x) {
    float y; asm("tanh.approx.f32 %0, %1;" : "=f"(y) : "f"(x)); return y;
}
__device__ __forceinline__ unsigned f2tf32(float f) {
    unsigned u; asm("cvt.rna.tf32.f32 %0, %1;" : "=r"(u) : "f"(f)); return u;
}
__device__ __forceinline__ void mma_tf32(float* c, const unsigned* a, const unsigned* b) {
    asm volatile(
        "mma.sync.aligned.m16n8k8.row.col.f32.tf32.tf32.f32 "
        "{%0,%1,%2,%3}, {%4,%5,%6,%7}, {%8,%9}, {%0,%1,%2,%3};"
        : "+f"(c[0]), "+f"(c[1]), "+f"(c[2]), "+f"(c[3])
        : "r"(a[0]), "r"(a[1]), "r"(a[2]), "r"(a[3]), "r"(b[0]), "r"(b[1]));
}
__device__ __forceinline__ void mma_f16(float* c, const unsigned* a, const unsigned* b) {
    asm volatile(
        "mma.sync.aligned.m16n8k16.row.col.f32.f16.f16.f32 "
        "{%0,%1,%2,%3}, {%4,%5,%6,%7}, {%8,%9}, {%0,%1,%2,%3};"
        : "+f"(c[0]), "+f"(c[1]), "+f"(c[2]), "+f"(c[3])
        : "r"(a[0]), "r"(a[1]), "r"(a[2]), "r"(a[3]), "r"(b[0]), "r"(b[1]));
}
__device__ __forceinline__ unsigned h2u(__half2 v) { return *(unsigned*)&v; }

// ---------------- prep: fused per-head weights ----------------
__global__ void __launch_bounds__(256) prep_fuse(
    const float* __restrict__ W1, const float* __restrict__ b1,
    const float* __restrict__ W2, const float* __restrict__ b2,
    const float* __restrict__ Wq, const float* __restrict__ bq,
    const float* __restrict__ Wk, const float* __restrict__ bk)
{
    int h   = blockIdx.x;
    int sel = blockIdx.y;
    int c0  = blockIdx.z * 64;
    const float* Wh   = sel ? W2 : W1;
    const float* bh_  = sel ? b2 : b1;
    const float* Wsrc = sel ? Wk : Wq;
    const float* bsrc = sel ? bk : bq;
    float* Wout = sel ? g_Wfk : g_Wfq;
    float* bout = sel ? g_bfk : g_bfq;
    __shared__ float Ws[DD][DD + 1];
    __shared__ float Ts[DD][DD + 1];
    int tid = threadIdx.x;
    for (int t = tid; t < DD * DD; t += 256) {
        Ws[t >> 6][t & 63] = Wh[t];
        Ts[t >> 6][t & 63] = Wsrc[(h * DD + (t >> 6)) * HIDN + c0 + (t & 63)];
    }
    __syncthreads();
    if (blockIdx.z == 0 && tid < DD) {
        float acc = bh_[tid];
        for (int j = 0; j < DD; j++) acc += Ws[tid][j] * bsrc[h * DD + j];
        bout[h * DD + tid] = acc;
    }
    int i = tid & 63;
    int g = tid >> 6;
#pragma unroll
    for (int cc = 0; cc < 16; cc++) {
        int c = g * 16 + cc;
        float acc = 0.f;
#pragma unroll 8
        for (int j = 0; j < DD; j++) acc = fmaf(Ws[i][j], Ts[j][c], acc);
        Wout[(h * DD + i) * HIDN + c0 + c] = acc;
    }
}

// ---------------- tf32 tensor-core GEMM: out = X @ W^T + bias ----------------
// mode 0: plain fp32 [m, HIDN]
// mode 3: Q-featurize -> g_FQ half [bh][l][256]
// mode 4: K-featurize -> g_FK half + g_ck
// mode 5: V half transposed -> g_Vh [bh][d][l]
__global__ void __launch_bounds__(256) gemm_tc(
    const float* __restrict__ X0, const float* __restrict__ Wm0, const float* __restrict__ B0, float* __restrict__ O0, int md0,
    const float* __restrict__ X1, const float* __restrict__ Wm1, const float* __restrict__ B1, float* __restrict__ O1, int md1,
    const float* __restrict__ X2, const float* __restrict__ Wm2, const float* __restrict__ B2, float* __restrict__ O2, int md2,
    const float* __restrict__ vw)
{
    const int BK = 32;
    int z = blockIdx.z;
    const float* X  = z == 0 ? X0  : (z == 1 ? X1  : X2);
    const float* W  = z == 0 ? Wm0 : (z == 1 ? Wm1 : Wm2);
    const float* Bi = z == 0 ? B0  : (z == 1 ? B1  : B2);
    float*       O  = z == 0 ? O0  : (z == 1 ? O1  : O2);
    int        mode = z == 0 ? md0 : (z == 1 ? md1 : md2);

    __shared__ union {
        struct { unsigned X[64][36]; unsigned W[64][36]; } st;  // 18432 B
        float out[64][68];                                      // 17408 B
    } sm;

    int tid = threadIdx.x;
    int lane = tid & 31;
    int warp = tid >> 5;
    int warp_m = (warp & 3) * 16;
    int warp_n = (warp >> 2) * 32;
    int gr = lane >> 2;
    int tg = lane & 3;
    int m0 = blockIdx.y * 64, n0 = blockIdx.x * 64;

    int ldr  = tid >> 3;
    int ldc4 = tid & 7;

    float acc[4][4];
#pragma unroll
    for (int nt = 0; nt < 4; nt++)
#pragma unroll
        for (int i = 0; i < 4; i++) acc[nt][i] = 0.f;

    float4 px[2], pw[2];
#pragma unroll
    for (int i = 0; i < 2; i++) {
        int r = ldr + i * 32;
        px[i] = *(const float4*)&X[(m0 + r) * HIDN + ldc4 * 4];
        pw[i] = *(const float4*)&W[(n0 + r) * HIDN + ldc4 * 4];
    }

    for (int kk = 0; kk < HIDN; kk += BK) {
#pragma unroll
        for (int i = 0; i < 2; i++) {
            int r = ldr + i * 32;
            uint4 ux, uw;
            ux.x = f2tf32(px[i].x); ux.y = f2tf32(px[i].y); ux.z = f2tf32(px[i].z); ux.w = f2tf32(px[i].w);
            uw.x = f2tf32(pw[i].x); uw.y = f2tf32(pw[i].y); uw.z = f2tf32(pw[i].z); uw.w = f2tf32(pw[i].w);
            *(uint4*)&sm.st.X[r][ldc4 * 4] = ux;
            *(uint4*)&sm.st.W[r][ldc4 * 4] = uw;
        }
        __syncthreads();
        if (kk + BK < HIDN) {
#pragma unroll
            for (int i = 0; i < 2; i++) {
                int r = ldr + i * 32;
                px[i] = *(const float4*)&X[(m0 + r) * HIDN + kk + BK + ldc4 * 4];
                pw[i] = *(const float4*)&W[(n0 + r) * HIDN + kk + BK + ldc4 * 4];
            }
        }
#pragma unroll
        for (int k8 = 0; k8 < 4; k8++) {
            int kb = k8 * 8;
            unsigned a[4], b[4][2];
            a[0] = sm.st.X[warp_m + gr    ][kb + tg];
            a[1] = sm.st.X[warp_m + gr + 8][kb + tg];
            a[2] = sm.st.X[warp_m + gr    ][kb + tg + 4];
            a[3] = sm.st.X[warp_m + gr + 8][kb + tg + 4];
#pragma unroll
            for (int nt = 0; nt < 4; nt++) {
                int rn = warp_n + nt * 8 + gr;
                b[nt][0] = sm.st.W[rn][kb + tg];
                b[nt][1] = sm.st.W[rn][kb + tg + 4];
            }
#pragma unroll
            for (int nt = 0; nt < 4; nt++)
                mma_tf32(acc[nt], a, b[nt]);
        }
        __syncthreads();
    }

#pragma unroll
    for (int nt = 0; nt < 4; nt++) {
        int col = warp_n + nt * 8 + 2 * tg;
        sm.out[warp_m + gr    ][col    ] = acc[nt][0];
        sm.out[warp_m + gr    ][col + 1] = acc[nt][1];
        sm.out[warp_m + gr + 8][col    ] = acc[nt][2];
        sm.out[warp_m + gr + 8][col + 1] = acc[nt][3];
    }
    __syncthreads();

    int b_ = m0 / LL, l0 = m0 - b_ * LL;
    int h = n0 >> 6;
    int bh = b_ * HH + h;

    if (mode == 0) {
#pragma unroll
        for (int i = 0; i < 4; i++) {
            int idx = tid + i * 256;
            int r = idx >> 4, c4 = idx & 15;
            float4 v = *(float4*)&sm.out[r][c4 * 4];
            float4 b4 = *(const float4*)&Bi[n0 + c4 * 4];
            v.x += b4.x; v.y += b4.y; v.z += b4.z; v.w += b4.w;
            *(float4*)&O[(m0 + r) * HIDN + n0 + c4 * 4] = v;
        }
    } else if (mode == 3 || mode == 4) {
        __half* Fdst = (mode == 3 ? g_FQ : g_FK) + (size_t)(bh * LL + l0) * FD;
#pragma unroll
        for (int i = 0; i < 4; i++) {
            int idx = tid + i * 256;
            int r = idx >> 4, c4 = idx & 15;
            int d0 = c4 * 4;
            float4 v = *(float4*)&sm.out[r][d0];
            float4 b4 = *(const float4*)&Bi[n0 + d0];
            float t0 = tanh_ap(v.x + b4.x), t1 = tanh_ap(v.y + b4.y);
            float t2 = tanh_ap(v.z + b4.z), t3 = tanh_ap(v.w + b4.w);
            float w0 = __ldg(&vw[d0]), w1 = __ldg(&vw[d0 + 1]);
            float w2 = __ldg(&vw[d0 + 2]), w3 = __ldg(&vw[d0 + 3]);
            __half* row = Fdst + (size_t)r * FD;
            if (mode == 3) {
                // FQ = [ta^2, vw*ta, ta^3, vw*ta^2]
                *(__half2*)&row[0*64 + d0    ] = __floats2half2_rn(t0*t0, t1*t1);
                *(__half2*)&row[0*64 + d0 + 2] = __floats2half2_rn(t2*t2, t3*t3);
                *(__half2*)&row[1*64 + d0    ] = __floats2half2_rn(w0*t0, w1*t1);
                *(__half2*)&row[1*64 + d0 + 2] = __floats2half2_rn(w2*t2, w3*t3);
                *(__half2*)&row[2*64 + d0    ] = __floats2half2_rn(t0*t0*t0, t1*t1*t1);
                *(__half2*)&row[2*64 + d0 + 2] = __floats2half2_rn(t2*t2*t2, t3*t3*t3);
                *(__half2*)&row[3*64 + d0    ] = __floats2half2_rn(w0*t0*t0, w1*t1*t1);
                *(__half2*)&row[3*64 + d0 + 2] = __floats2half2_rn(w2*t2*t2, w3*t3*t3);
            } else {
                // FK = [-vw*tb, -tb^2, vw*tb^2, tb^3]
                *(__half2*)&row[0*64 + d0    ] = __floats2half2_rn(-w0*t0, -w1*t1);
                *(__half2*)&row[0*64 + d0 + 2] = __floats2half2_rn(-w2*t2, -w3*t3);
                *(__half2*)&row[1*64 + d0    ] = __floats2half2_rn(-t0*t0, -t1*t1);
                *(__half2*)&row[1*64 + d0 + 2] = __floats2half2_rn(-t2*t2, -t3*t3);
                *(__half2*)&row[2*64 + d0    ] = __floats2half2_rn(w0*t0*t0, w1*t1*t1);
                *(__half2*)&row[2*64 + d0 + 2] = __floats2half2_rn(w2*t2*t2, w3*t3*t3);
                *(__half2*)&row[3*64 + d0    ] = __floats2half2_rn(t0*t0*t0, t1*t1*t1);
                *(__half2*)&row[3*64 + d0 + 2] = __floats2half2_rn(t2*t2*t2, t3*t3*t3);
                // ck[l] = sum_d vw*tb   (reduce across the 16 lanes sharing row r)
                float cp = w0*t0 + w1*t1 + w2*t2 + w3*t3;
#pragma unroll
                for (int o = 1; o < 16; o <<= 1) cp += __shfl_xor_sync(0xffffffffu, cp, o);
                if ((tid & 15) == 0) g_ck[bh * LL + l0 + r] = cp;
            }
        }
    } else {
        // mode 5: V -> half, transposed [bh][d][l]
        __half* base = g_Vh + (size_t)bh * DD * LL;
#pragma unroll
        for (int i = 0; i < 4; i++) {
            int idx = tid + i * 256;
            int d = idx >> 4, l4 = idx & 15;
            float bd = __ldg(&Bi[n0 + d]);
            float v0 = sm.out[l4 * 4 + 0][d] + bd;
            float v1 = sm.out[l4 * 4 + 1][d] + bd;
            float v2 = sm.out[l4 * 4 + 2][d] + bd;
            float v3 = sm.out[l4 * 4 + 3][d] + bd;
            *(__half2*)&base[d * LL + l0 + l4 * 4    ] = __floats2half2_rn(v0, v1);
            *(__half2*)&base[d * LL + l0 + l4 * 4 + 2] = __floats2half2_rn(v2, v3);
        }
    }
}

// ---------------- attention: E = FQ@FK^T + ck -> softmax -> X = P@V (all f16 MMA) ----
#define LLP 392
#define FDP 264
#define VHS 72
#define EOFF  0
#define UOFF  (32*LLP*4)                       // 50176
#define FQOFF UOFF
#define FKOFF (UOFF + 32*FDP*2)                // +16896
#define VHOFF UOFF
#define CKOFF (UOFF + 32*FDP*2 + 64*FDP*2)     // 100864
#define MOFF  (CKOFF + LL*4)                   // 102400
#define SMEM_ATTN (MOFF + LL*4)                // 103936

__global__ void __launch_bounds__(256) attn_fused(
    const int* __restrict__ mask, float* __restrict__ attn)
{
    extern __shared__ char smraw[];
    float*  E  = (float*) (smraw + EOFF);   // [32][LLP]
    __half* FQ = (__half*)(smraw + FQOFF);  // [32][FDP]
    __half* FK = (__half*)(smraw + FKOFF);  // [64][FDP]
    __half* Vh = (__half*)(smraw + VHOFF);  // [64][VHS]
    float*  CK = (float*) (smraw + CKOFF);
    int*    M  = (int*)   (smraw + MOFF);

    int tid = threadIdx.x;
    int lane = tid & 31, warp = tid >> 5;
    int wm = (warp & 1) * 16;         // m offset (q)
    int wn = (warp >> 1) * 16;        // n offset within 64 chunk
    int gr = lane >> 2, tg = lane & 3;
    int bh = blockIdx.y, b = bh >> 3, h = bh & 7;
    int q0 = blockIdx.x * 32;

    for (int j = tid; j < LL; j += 256) { M[j] = mask[b * LL + j]; CK[j] = g_ck[bh * LL + j]; }
    {
        const unsigned* s32 = (const unsigned*)(g_FQ + (size_t)(bh * LL + q0) * FD);
#pragma unroll
        for (int i = 0; i < 16; i++) {
            int idx = tid + i * 256;          // 0..4095 half2
            int r = idx >> 7, c2 = idx & 127;
            *(unsigned*)&FQ[r * FDP + c2 * 2] = s32[r * 128 + c2];
        }
    }

    // ---- E = FQ @ FK^T ----
    for (int c = 0; c < 6; c++) {
        __syncthreads();
        {
            const unsigned* s32 = (const unsigned*)(g_FK + (size_t)(bh * LL + c * 64) * FD);
#pragma unroll
            for (int i = 0; i < 32; i++) {
                int idx = tid + i * 256;      // 0..8191 half2
                int r = idx >> 7, c2 = idx & 127;
                *(unsigned*)&FK[r * FDP + c2 * 2] = s32[r * 128 + c2];
            }
        }
        __syncthreads();
        float eacc[2][4];
#pragma unroll
        for (int nt = 0; nt < 2; nt++)
#pragma unroll
            for (int i = 0; i < 4; i++) eacc[nt][i] = 0.f;
#pragma unroll
        for (int ks = 0; ks < 16; ks++) {
            int k0 = ks * 16;
            unsigned a[4], bf[2][2];
            a[0] = *(const unsigned*)&FQ[(wm + gr    ) * FDP + k0 + 2 * tg];
            a[1] = *(const unsigned*)&FQ[(wm + gr + 8) * FDP + k0 + 2 * tg];
            a[2] = *(const unsigned*)&FQ[(wm + gr    ) * FDP + k0 + 2 * tg + 8];
            a[3] = *(const unsigned*)&FQ[(wm + gr + 8) * FDP + k0 + 2 * tg + 8];
#pragma unroll
            for (int nt = 0; nt < 2; nt++) {
                int rn = wn + nt * 8 + gr;
                bf[nt][0] = *(const unsigned*)&FK[rn * FDP + k0 + 2 * tg];
                bf[nt][1] = *(const unsigned*)&FK[rn * FDP + k0 + 2 * tg + 8];
            }
            mma_f16(eacc[0], a, bf[0]);
            mma_f16(eacc[1], a, bf[1]);
        }
#pragma unroll
        for (int nt = 0; nt < 2; nt++) {
            int col = c * 64 + wn + nt * 8 + 2 * tg;
            *(float2*)&E[(wm + gr    ) * LLP + col] = make_float2(eacc[nt][0], eacc[nt][1]);
            *(float2*)&E[(wm + gr + 8) * LLP + col] = make_float2(eacc[nt][2], eacc[nt][3]);
        }
    }
    __syncthreads();

    // ---- softmax: row = tid>>3 (32 rows), 8 lanes per row, 48 cols each ----
    {
        int row = tid >> 3, lx = tid & 7;
        float mx = -3.0e38f;
        for (int i = 0; i < 48; i++) {
            int j = lx + i * 8;
            float e = E[row * LLP + j] + CK[j];
            if (M[j] == 0) e = -1e10f;
            E[row * LLP + j] = e;
            mx = fmaxf(mx, e);
        }
#pragma unroll
        for (int o = 4; o > 0; o >>= 1) mx = fmaxf(mx, __shfl_xor_sync(0xffffffffu, mx, o));
        float sum = 0.f;
        for (int i = 0; i < 48; i++) {
            int j = lx + i * 8;
            float p = __expf(E[row * LLP + j] - mx);
            sum += p;
            E[row * LLP + j] = p;
        }
#pragma unroll
        for (int o = 4; o > 0; o >>= 1) sum += __shfl_xor_sync(0xffffffffu, sum, o);
        float inv = __frcp_rn(sum);
        for (int i = 0; i < 48; i++) E[row * LLP + lx + i * 8] *= inv;
    }
    __syncthreads();

    // coalesced attn store
    {
        float* dst = attn + (size_t)(bh * LL + q0) * LL;
        for (int idx = tid; idx < 32 * LL; idx += 256) {
            int r = idx / LL, j = idx - r * LL;
            dst[r * LL + j] = E[r * LLP + j];
        }
    }

    // ---- X = P @ V  (P cvt f32->f16 on load; V half [d][l] chunks) ----
    float xacc[2][4];
#pragma unroll
    for (int nt = 0; nt < 2; nt++)
#pragma unroll
        for (int i = 0; i < 4; i++) xacc[nt][i] = 0.f;

    for (int c = 0; c < 6; c++) {
        __syncthreads();
        {
            const unsigned* s32 = (const unsigned*)(g_Vh + (size_t)bh * DD * LL + c * 64);
#pragma unroll
            for (int i = 0; i < 8; i++) {
                int idx = tid + i * 256;      // 0..2047 half2
                int d = idx >> 5, c2 = idx & 31;
                *(unsigned*)&Vh[d * VHS + c2 * 2] = s32[d * (LL / 2) + c2];
            }
        }
        __syncthreads();
#pragma unroll
        for (int ks = 0; ks < 4; ks++) {
            int kg = c * 64 + ks * 16;
            unsigned a[4], bf[2][2];
            float2 p0 = *(const float2*)&E[(wm + gr    ) * LLP + kg + 2 * tg];
            float2 p1 = *(const float2*)&E[(wm + gr + 8) * LLP + kg + 2 * tg];
            float2 p2 = *(const float2*)&E[(wm + gr    ) * LLP + kg + 2 * tg + 8];
            float2 p3 = *(const float2*)&E[(wm + gr + 8) * LLP + kg + 2 * tg + 8];
            a[0] = h2u(__floats2half2_rn(p0.x, p0.y));
            a[1] = h2u(__floats2half2_rn(p1.x, p1.y));
            a[2] = h2u(__floats2half2_rn(p2.x, p2.y));
            a[3] = h2u(__floats2half2_rn(p3.x, p3.y));
            int kl = ks * 16 + 2 * tg;
#pragma unroll
            for (int nt = 0; nt < 2; nt++) {
                int rn = wn + nt * 8 + gr;
                bf[nt][0] = *(const unsigned*)&Vh[rn * VHS + kl];
                bf[nt][1] = *(const unsigned*)&Vh[rn * VHS + kl + 8];
            }
            mma_f16(xacc[0], a, bf[0]);
            mma_f16(xacc[1], a, bf[1]);
        }
    }

    // X store: [b*LL + q][512] at head offset
    {
        int q = q0 + wm + gr;
#pragma unroll
        for (int nt = 0; nt < 2; nt++) {
            int d = h * DD + wn + nt * 8 + 2 * tg;
            *(float2*)&g_X[(size_t)(b * LL + q    ) * HIDN + d] = make_float2(xacc[nt][0], xacc[nt][1]);
            *(float2*)&g_X[(size_t)(b * LL + q + 8) * HIDN + d] = make_float2(xacc[nt][2], xacc[nt][3]);
        }
    }
}

extern "C" void kernel_launch(void* const* d_in, const int* in_sizes, int n_in,
                              void* d_out, int out_size)
{
    const float* query = (const float*)d_in[0];
    const float* key_  = (const float*)d_in[1];
    const float* value = (const float*)d_in[2];
    const int*   mask  = (const int*)  d_in[3];
    const float* Wq = (const float*)d_in[4];
    const float* bq = (const float*)d_in[5];
    const float* Wk = (const float*)d_in[6];
    const float* bk = (const float*)d_in[7];
    const float* Wv = (const float*)d_in[8];
    const float* bv = (const float*)d_in[9];
    const float* Wo = (const float*)d_in[10];
    const float* bo = (const float*)d_in[11];
    const float* W1 = (const float*)d_in[12];
    const float* b1 = (const float*)d_in[13];
    const float* W2 = (const float*)d_in[14];
    const float* b2 = (const float*)d_in[15];
    const float* vw = (const float*)d_in[16];
    (void)d_in[17]; // vb cancels in softmax; raw energy never output
    (void)in_sizes; (void)n_in;

    float* out = (float*)d_out;

    float *gX, *gA, *gWfq, *gWfk, *gbfq, *gbfk;
    cudaGetSymbolAddress((void**)&gX,   g_X);
    cudaGetSymbolAddress((void**)&gA,   g_attn);
    cudaGetSymbolAddress((void**)&gWfq, g_Wfq);
    cudaGetSymbolAddress((void**)&gWfk, g_Wfk);
    cudaGetSymbolAddress((void**)&gbfq, g_bfq);
    cudaGetSymbolAddress((void**)&gbfk, g_bfk);

    float* attn_dst = (out_size >= X_ELEMS + A_ELEMS) ? (out + X_ELEMS) : gA;

    cudaFuncSetAttribute(attn_fused, cudaFuncAttributeMaxDynamicSharedMemorySize, SMEM_ATTN);

    // 1) fuse W1@Wq and W2@Wk (128 blocks)
    prep_fuse<<<dim3(HH, 2, HIDN / 64), 256>>>(W1, b1, W2, b2, Wq, bq, Wk, bk);

    // 2) projections + featurization — tf32 TC, 288 blocks
    gemm_tc<<<dim3(HIDN / 64, MROWS / 64, 3), 256>>>(
        query, gWfq, gbfq, nullptr, 3,
        key_,  gWfk, gbfk, nullptr, 4,
        value, Wv,   bv,   nullptr, 5,
        vw);

    // 3) attention: E-mma + softmax + AV-mma (192 blocks, dyn smem)
    attn_fused<<<dim3(LL / 32, BH), 256, SMEM_ATTN>>>(mask, attn_dst);

    // 4) output projection — tf32 TC (96 blocks)
    gemm_tc<<<dim3(HIDN / 64, MROWS / 64, 1), 256>>>(
        gX, Wo, bo, out, 0,
        gX, Wo, bo, out, 0,
        gX, Wo, bo, out, 0,
        vw);
}